// round 7
// baseline (speedup 1.0000x reference)
#include <cuda_runtime.h>
#include <cuda_bf16.h>
#include <cstdint>
#include <math.h>

// Problem constants
#define M_ROWS 32768
#define EDIM   768
#define NHEAD  12
#define HDIM   64
#define PDIM   256
#define BT     128
#define WSZ    (EDIM * EDIM)

// Scratch (allocation-free rule: __device__ globals)
__device__ float g_q[M_ROWS * EDIM];
__device__ float g_k[M_ROWS * EDIM];
__device__ float g_yf[M_ROWS * EDIM];
__device__ int8_t g_x1[M_ROWS * EDIM];
__device__ int8_t g_x2[M_ROWS * EDIM];
__device__ int8_t g_y1[M_ROWS * EDIM];
__device__ int8_t g_y2[M_ROWS * EDIM];
__device__ float  g_sx[M_ROWS];
__device__ float  g_sy[M_ROWS];
__device__ int8_t g_w1[4 * WSZ];
__device__ int8_t g_w2[4 * WSZ];
__device__ float  g_sw[4 * EDIM];
__device__ __nv_bfloat16 g_qhi[M_ROWS * EDIM];
__device__ __nv_bfloat16 g_qlo[M_ROWS * EDIM];
__device__ __nv_bfloat16 g_khi[M_ROWS * EDIM];
__device__ __nv_bfloat16 g_klo[M_ROWS * EDIM];
__device__ __nv_bfloat16 g_vhi[M_ROWS * EDIM];
__device__ __nv_bfloat16 g_vlo[M_ROWS * EDIM];

// ---------------------------------------------------------------------------
// helpers
// ---------------------------------------------------------------------------
__device__ __forceinline__ uint32_t smem_u32(const void* p)
{
    uint32_t a;
    asm("{ .reg .u64 t; cvta.to.shared.u64 t, %1; cvt.u32.u64 %0, t; }"
        : "=r"(a) : "l"(p));
    return a;
}

__device__ __forceinline__ void ldsm_x4(uint32_t* r, uint32_t addr)
{
    asm volatile("ldmatrix.sync.aligned.m8n8.x4.shared.b16 {%0,%1,%2,%3}, [%4];"
        : "=r"(r[0]), "=r"(r[1]), "=r"(r[2]), "=r"(r[3]) : "r"(addr));
}

__device__ __forceinline__ void ldsm_x2(uint32_t* r, uint32_t addr)
{
    asm volatile("ldmatrix.sync.aligned.m8n8.x2.shared.b16 {%0,%1}, [%2];"
        : "=r"(r[0]), "=r"(r[1]) : "r"(addr));
}

__device__ __forceinline__ void ldsm_x2t(uint32_t* r, uint32_t addr)
{
    asm volatile("ldmatrix.sync.aligned.m8n8.x2.trans.shared.b16 {%0,%1}, [%2];"
        : "=r"(r[0]), "=r"(r[1]) : "r"(addr));
}

__device__ __forceinline__ void mma16816(float* c, const uint32_t* a, const uint32_t* b)
{
    asm volatile("mma.sync.aligned.m16n8k16.row.col.f32.bf16.bf16.f32 "
        "{%0,%1,%2,%3},{%4,%5,%6,%7},{%8,%9},{%0,%1,%2,%3};"
        : "+f"(c[0]), "+f"(c[1]), "+f"(c[2]), "+f"(c[3])
        : "r"(a[0]), "r"(a[1]), "r"(a[2]), "r"(a[3]), "r"(b[0]), "r"(b[1]));
}

__device__ __forceinline__ void mma_i8(int* c, const uint32_t* a, const uint32_t* b)
{
    asm volatile("mma.sync.aligned.m16n8k32.row.col.s32.s8.s8.s32 "
        "{%0,%1,%2,%3},{%4,%5,%6,%7},{%8,%9},{%0,%1,%2,%3};"
        : "+r"(c[0]), "+r"(c[1]), "+r"(c[2]), "+r"(c[3])
        : "r"(a[0]), "r"(a[1]), "r"(a[2]), "r"(a[3]), "r"(b[0]), "r"(b[1]));
}

__device__ __forceinline__ void cp16(uint32_t saddr, const void* g)
{
    asm volatile("cp.async.cg.shared.global [%0], [%1], 16;"
        :: "r"(saddr), "l"(g) : "memory");
}
#define CP_COMMIT() asm volatile("cp.async.commit_group;" ::: "memory")
#define CP_WAIT1()  asm volatile("cp.async.wait_group 1;" ::: "memory")
#define CP_WAIT0()  asm volatile("cp.async.wait_group 0;" ::: "memory")

__device__ __forceinline__ uint32_t pack2(float x, float y)
{
    __nv_bfloat16 h0 = __float2bfloat16(x);
    __nv_bfloat16 h1 = __float2bfloat16(y);
    uint32_t u0 = (uint32_t)__bfloat16_as_ushort(h0);
    uint32_t u1 = (uint32_t)__bfloat16_as_ushort(h1);
    return u0 | (u1 << 16);
}

__device__ __forceinline__ void split2(float a, float b, uint32_t* hi, uint32_t* lo)
{
    __nv_bfloat16 ha = __float2bfloat16(a);
    __nv_bfloat16 hb = __float2bfloat16(b);
    *hi = (uint32_t)__bfloat16_as_ushort(ha) | ((uint32_t)__bfloat16_as_ushort(hb) << 16);
    *lo = pack2(a - __bfloat162float(ha), b - __bfloat162float(hb));
}

// ---------------------------------------------------------------------------
// per-row int8 two-slice quantization: in[row][768] -> q1,q2 int8, scale[row]
// one warp per row, 8 rows per block
// ---------------------------------------------------------------------------
__global__ void quant_rows(const float* __restrict__ in,
                           int8_t* __restrict__ q1, int8_t* __restrict__ q2,
                           float* __restrict__ sc)
{
    const int w    = threadIdx.x >> 5;
    const int lane = threadIdx.x & 31;
    const int row  = blockIdx.x * 8 + w;

    const float4* p = (const float4*)(in + (size_t)row * EDIM);
    float4 v[6];
    float mx = 0.0f;
    #pragma unroll
    for (int i = 0; i < 6; i++) {
        v[i] = p[lane + 32 * i];
        mx = fmaxf(mx, fmaxf(fmaxf(fabsf(v[i].x), fabsf(v[i].y)),
                             fmaxf(fabsf(v[i].z), fabsf(v[i].w))));
    }
    #pragma unroll
    for (int o = 16; o > 0; o >>= 1) {
        mx = fmaxf(mx, __shfl_xor_sync(0xffffffffu, mx, o));
    }
    const float sa  = (mx > 0.0f) ? mx * (1.0f / 127.0f) : 1.0f;
    const float inv = 1.0f / sa;
    if (lane == 0) sc[row] = sa;

    uint32_t* o1 = (uint32_t*)(q1 + (size_t)row * EDIM);
    uint32_t* o2 = (uint32_t*)(q2 + (size_t)row * EDIM);
    #pragma unroll
    for (int i = 0; i < 6; i++) {
        float f[4];
        f[0] = v[i].x; f[1] = v[i].y; f[2] = v[i].z; f[3] = v[i].w;
        uint32_t p1 = 0;
        uint32_t p2 = 0;
        #pragma unroll
        for (int e = 0; e < 4; e++) {
            int a = __float2int_rn(f[e] * inv);
            float r = f[e] - (float)a * sa;
            int b = __float2int_rn(r * inv * 128.0f);
            p1 |= (uint32_t)(a & 255) << (8 * e);
            p2 |= (uint32_t)(b & 255) << (8 * e);
        }
        o1[lane + 32 * i] = p1;
        o2[lane + 32 * i] = p2;
    }
}

// ---------------------------------------------------------------------------
// weight transpose + per-output-column int8 two-slice quant:
// W[K][N] -> q1T,q2T [N][K], scale[n]. One warp per n.
// ---------------------------------------------------------------------------
__global__ void wquantT(const float* __restrict__ W,
                        int8_t* __restrict__ q1T, int8_t* __restrict__ q2T,
                        float* __restrict__ sc)
{
    const int w    = threadIdx.x >> 5;
    const int lane = threadIdx.x & 31;
    const int n    = blockIdx.x * 8 + w;

    float vals[24];
    float mx = 0.0f;
    #pragma unroll
    for (int i = 0; i < 24; i++) {
        vals[i] = W[(size_t)(lane + 32 * i) * EDIM + n];
        mx = fmaxf(mx, fabsf(vals[i]));
    }
    #pragma unroll
    for (int o = 16; o > 0; o >>= 1) {
        mx = fmaxf(mx, __shfl_xor_sync(0xffffffffu, mx, o));
    }
    const float sa  = (mx > 0.0f) ? mx * (1.0f / 127.0f) : 1.0f;
    const float inv = 1.0f / sa;
    if (lane == 0) sc[n] = sa;

    #pragma unroll
    for (int i = 0; i < 24; i++) {
        int a = __float2int_rn(vals[i] * inv);
        float r = vals[i] - (float)a * sa;
        int b = __float2int_rn(r * inv * 128.0f);
        q1T[(size_t)n * EDIM + lane + 32 * i] = (int8_t)a;
        q2T[(size_t)n * EDIM + lane + 32 * i] = (int8_t)b;
    }
}

// ---------------------------------------------------------------------------
// int8 Ozaki GEMM: C = sA.sB.(A1B1 + (A1B2 + A2B1)/128) (+bias).
// B* hold BT [N][K]. 128x128x64 CTA tile, 8 warps (2x4), warp 64x32 via
// m16n8k32 s8 mma, s32 accumulators (exact). cp.async double buffered.
// Output fp32 (C) or split bf16 (Chi/Clo) when Chi != 0.
// ---------------------------------------------------------------------------
#define TB8 10240                        // 128 rows x 80B
#define GEMM_SMEM (2 * 4 * TB8)          // 81920

__global__ __launch_bounds__(256, 1) void gemm_i8(
    const int8_t* __restrict__ A1, const int8_t* __restrict__ A2,
    const float* __restrict__ sA,
    const int8_t* __restrict__ B1, const int8_t* __restrict__ B2,
    const float* __restrict__ sB,
    const float* __restrict__ bias, float* __restrict__ C,
    __nv_bfloat16* __restrict__ Chi, __nv_bfloat16* __restrict__ Clo,
    int M, int N, int K)
{
    extern __shared__ char sm[];

    const int tid  = threadIdx.x;
    const int bm   = blockIdx.y * 128;
    const int bn   = blockIdx.x * 128;
    const int warp = tid >> 5;
    const int lane = tid & 31;
    const int wm   = warp >> 2;
    const int wn   = warp & 3;

    const int r  = tid >> 1;
    const int ch = (tid & 1) * 32;

    const int8_t* gA1 = A1 + (size_t)(bm + r) * K + ch;
    const int8_t* gA2 = A2 + (size_t)(bm + r) * K + ch;
    const int8_t* gB1 = B1 + (size_t)(bn + r) * K + ch;
    const int8_t* gB2 = B2 + (size_t)(bn + r) * K + ch;

    const uint32_t sb     = smem_u32(sm);
    const uint32_t st_off = (uint32_t)(r * 80 + ch);

    const int lane15 = lane & 15;
    const uint32_t aoff = (uint32_t)((wm * 64 + lane15) * 80 + (lane >> 4) * 16);
    const uint32_t boff = (uint32_t)((wn * 32 + (lane15 & 7)) * 80 + ((lane15 >> 3) & 1) * 16);

    int a11[4][4][4];
    int axx[4][4][4];
    #pragma unroll
    for (int i = 0; i < 4; i++) {
        #pragma unroll
        for (int j = 0; j < 4; j++) {
            #pragma unroll
            for (int e = 0; e < 4; e++) {
                a11[i][j][e] = 0;
                axx[i][j][e] = 0;
            }
        }
    }

    const int NIT = K / 64;   // 12

    {
        const uint32_t base = sb + st_off;
        cp16(base + 0 * TB8,      gA1);
        cp16(base + 0 * TB8 + 16, gA1 + 16);
        cp16(base + 1 * TB8,      gA2);
        cp16(base + 1 * TB8 + 16, gA2 + 16);
        cp16(base + 2 * TB8,      gB1);
        cp16(base + 2 * TB8 + 16, gB1 + 16);
        cp16(base + 3 * TB8,      gB2);
        cp16(base + 3 * TB8 + 16, gB2 + 16);
        CP_COMMIT();
    }

    for (int it = 0; it < NIT; it++) {
        const int s = it & 1;

        if (it + 1 < NIT) {
            const int kt = (it + 1) * 64;
            const uint32_t base = sb + (uint32_t)((s ^ 1) * 4) * TB8 + st_off;
            cp16(base + 0 * TB8,      gA1 + kt);
            cp16(base + 0 * TB8 + 16, gA1 + kt + 16);
            cp16(base + 1 * TB8,      gA2 + kt);
            cp16(base + 1 * TB8 + 16, gA2 + kt + 16);
            cp16(base + 2 * TB8,      gB1 + kt);
            cp16(base + 2 * TB8 + 16, gB1 + kt + 16);
            cp16(base + 3 * TB8,      gB2 + kt);
            cp16(base + 3 * TB8 + 16, gB2 + kt + 16);
            CP_COMMIT();
            CP_WAIT1();
        } else {
            CP_WAIT0();
        }
        __syncthreads();

        const uint32_t baA1 = sb + (uint32_t)(s * 4 + 0) * TB8;
        const uint32_t baA2 = sb + (uint32_t)(s * 4 + 1) * TB8;
        const uint32_t baB1 = sb + (uint32_t)(s * 4 + 2) * TB8;
        const uint32_t baB2 = sb + (uint32_t)(s * 4 + 3) * TB8;

        #pragma unroll
        for (int ks = 0; ks < 2; ks++) {
            const uint32_t kb = (uint32_t)(ks * 32);
            uint32_t af1[4][4];
            uint32_t af2[4][4];
            uint32_t bf1[4][2];
            uint32_t bf2[4][2];
            #pragma unroll
            for (int mf = 0; mf < 4; mf++) {
                ldsm_x4(af1[mf], baA1 + aoff + mf * 1280 + kb);
                ldsm_x4(af2[mf], baA2 + aoff + mf * 1280 + kb);
            }
            #pragma unroll
            for (int nf = 0; nf < 4; nf++) {
                ldsm_x2(bf1[nf], baB1 + boff + nf * 640 + kb);
                ldsm_x2(bf2[nf], baB2 + boff + nf * 640 + kb);
            }
            #pragma unroll
            for (int mf = 0; mf < 4; mf++) {
                #pragma unroll
                for (int nf = 0; nf < 4; nf++) {
                    mma_i8(a11[mf][nf], af1[mf], bf1[nf]);
                    mma_i8(axx[mf][nf], af1[mf], bf2[nf]);
                    mma_i8(axx[mf][nf], af2[mf], bf1[nf]);
                }
            }
        }
        __syncthreads();
    }

    const int rbase = bm + wm * 64 + (lane >> 2);
    const int cbase = bn + wn * 32 + (lane & 3) * 2;
    #pragma unroll
    for (int nf = 0; nf < 4; nf++) {
        const int col = cbase + nf * 8;
        const float sb0 = sB[col];
        const float sb1 = sB[col + 1];
        float bb0 = 0.0f;
        float bb1 = 0.0f;
        if (bias != 0) {
            bb0 = bias[col];
            bb1 = bias[col + 1];
        }
        #pragma unroll
        for (int mf = 0; mf < 4; mf++) {
            const int row = rbase + mf * 16;
            const float sa0 = sA[row];
            const float sa1 = sA[row + 8];
            const float f0 = (float)a11[mf][nf][0] + (float)axx[mf][nf][0] * 0.0078125f;
            const float f1 = (float)a11[mf][nf][1] + (float)axx[mf][nf][1] * 0.0078125f;
            const float f2 = (float)a11[mf][nf][2] + (float)axx[mf][nf][2] * 0.0078125f;
            const float f3 = (float)a11[mf][nf][3] + (float)axx[mf][nf][3] * 0.0078125f;
            const float c0 = sa0 * sb0 * f0 + bb0;
            const float c1 = sa0 * sb1 * f1 + bb1;
            const float c2 = sa1 * sb0 * f2 + bb0;
            const float c3 = sa1 * sb1 * f3 + bb1;
            if (Chi != 0) {
                uint32_t h0, l0, h1, l1;
                split2(c0, c1, &h0, &l0);
                split2(c2, c3, &h1, &l1);
                *(uint32_t*)(Chi + (size_t)row * N + col)       = h0;
                *(uint32_t*)(Clo + (size_t)row * N + col)       = l0;
                *(uint32_t*)(Chi + (size_t)(row + 8) * N + col) = h1;
                *(uint32_t*)(Clo + (size_t)(row + 8) * N + col) = l1;
            } else {
                float2 v0;
                float2 v1;
                v0.x = c0; v0.y = c1;
                v1.x = c2; v1.y = c3;
                *(float2*)(C + (size_t)row * N + col)       = v0;
                *(float2*)(C + (size_t)(row + 8) * N + col) = v1;
            }
        }
    }
}

// ---------------------------------------------------------------------------
// 2-D RoPE: reads fp32 q or k, writes rotated values as bf16 hi/lo.
// ---------------------------------------------------------------------------
__global__ void rope_split_kernel(const float* __restrict__ q, const float* __restrict__ k,
                                  __nv_bfloat16* __restrict__ qhi, __nv_bfloat16* __restrict__ qlo,
                                  __nv_bfloat16* __restrict__ khi, __nv_bfloat16* __restrict__ klo)
{
    const int t = blockIdx.x * blockDim.x + threadIdx.x;
    const float* buf = (blockIdx.y == 0) ? q : k;
    __nv_bfloat16* ohi = (blockIdx.y == 0) ? qhi : khi;
    __nv_bfloat16* olo = (blockIdx.y == 0) ? qlo : klo;

    const int rem = t % 384;
    const int row = t / 384;
    const int pr  = rem & 31;
    const int p   = row & 255;
    const int j   = pr & 15;
    const float pos = (pr < 16) ? (float)(p & 15) : (float)(p >> 4);

    const float ang = pos * __expf(-0.57564627324851142f * (float)j);
    float s;
    float c;
    sincosf(ang, &s, &c);

    const size_t off = (size_t)t * 2;
    const float x0 = buf[off];
    const float x1 = buf[off + 1];
    const float a = x0 * c - x1 * s;
    const float b = x1 * c + x0 * s;

    uint32_t hw, lw;
    split2(a, b, &hw, &lw);
    ((uint32_t*)ohi)[t] = hw;
    ((uint32_t*)olo)[t] = lw;
}

// ---------------------------------------------------------------------------
// Tensor-core attention (bf16 hi/lo 3-product). Writes y as fp32.
// ---------------------------------------------------------------------------
#define SROWB   144
#define ATILEB  (64 * SROWB)
#define ASTGB   (4 * ATILEB)
#define ATTN_SMEM (2 * ASTGB)

__global__ __launch_bounds__(256, 1) void attn_mma(
    const __nv_bfloat16* __restrict__ qhi, const __nv_bfloat16* __restrict__ qlo,
    const __nv_bfloat16* __restrict__ khi, const __nv_bfloat16* __restrict__ klo,
    const __nv_bfloat16* __restrict__ vhi, const __nv_bfloat16* __restrict__ vlo,
    float* __restrict__ yf)
{
    extern __shared__ char sm[];

    const int tid   = threadIdx.x;
    const int warp  = tid >> 5;
    const int lane  = tid & 31;
    const int l4    = lane >> 2;
    const int l2    = (lane & 3) * 2;
    const int lane15 = lane & 15;

    const int bt   = blockIdx.x;
    const int h    = blockIdx.y >> 1;
    const int half = blockIdx.y & 1;

    const int qrow0 = bt * 256 + half * 128 + warp * 16;
    const uint32_t sb = smem_u32(sm);

    uint32_t qh[4][4];
    uint32_t ql[4][4];
    {
        const size_t qb = (size_t)(qrow0 + l4) * EDIM + h * 64;
        #pragma unroll
        for (int kf = 0; kf < 4; kf++) {
            const int c = kf * 16 + l2;
            qh[kf][0] = *(const uint32_t*)(qhi + qb + c);
            qh[kf][1] = *(const uint32_t*)(qhi + qb + (size_t)8 * EDIM + c);
            qh[kf][2] = *(const uint32_t*)(qhi + qb + c + 8);
            qh[kf][3] = *(const uint32_t*)(qhi + qb + (size_t)8 * EDIM + c + 8);
            ql[kf][0] = *(const uint32_t*)(qlo + qb + c);
            ql[kf][1] = *(const uint32_t*)(qlo + qb + (size_t)8 * EDIM + c);
            ql[kf][2] = *(const uint32_t*)(qlo + qb + c + 8);
            ql[kf][3] = *(const uint32_t*)(qlo + qb + (size_t)8 * EDIM + c + 8);
        }
    }

    float O[8][4];
    #pragma unroll
    for (int nf = 0; nf < 8; nf++) {
        #pragma unroll
        for (int e = 0; e < 4; e++) {
            O[nf][e] = 0.0f;
        }
    }
    float sum0 = 0.0f;
    float sum1 = 0.0f;

    const int lrow0 = tid >> 3;
    const int lseg0 = tid & 7;
    const int lrow1 = (tid + 256) >> 3;
    const int lseg1 = tid & 7;

    #define ATTN_LOAD(c, s) do {                                                   \
        const int jg0 = bt * 256 + (c) * 64;                                        \
        const uint32_t base = sb + (uint32_t)(s) * ASTGB;                           \
        size_t g0 = (size_t)(jg0 + lrow0) * EDIM + h * 64 + lseg0 * 8;              \
        uint32_t d0 = base + (uint32_t)(lrow0 * SROWB + lseg0 * 16);                \
        cp16(d0 + 0 * ATILEB, khi + g0);                                            \
        cp16(d0 + 1 * ATILEB, klo + g0);                                            \
        cp16(d0 + 2 * ATILEB, vhi + g0);                                            \
        cp16(d0 + 3 * ATILEB, vlo + g0);                                            \
        size_t g1 = (size_t)(jg0 + lrow1) * EDIM + h * 64 + lseg1 * 8;              \
        uint32_t d1 = base + (uint32_t)(lrow1 * SROWB + lseg1 * 16);                \
        cp16(d1 + 0 * ATILEB, khi + g1);                                            \
        cp16(d1 + 1 * ATILEB, klo + g1);                                            \
        cp16(d1 + 2 * ATILEB, vhi + g1);                                            \
        cp16(d1 + 3 * ATILEB, vlo + g1);                                            \
        CP_COMMIT();                                                                \
    } while (0)

    ATTN_LOAD(0, 0);

    const uint32_t bqoff = (uint32_t)((lane15 & 7) * SROWB + ((lane15 >> 3) & 1) * 16);
    const uint32_t bvoff = (uint32_t)(lane15 * SROWB);

    for (int c = 0; c < 4; c++) {
        const int s = c & 1;
        if (c < 3) {
            ATTN_LOAD(c + 1, s ^ 1);
            CP_WAIT1();
        } else {
            CP_WAIT0();
        }
        __syncthreads();

        const uint32_t kb = sb + (uint32_t)s * ASTGB;

        float S[8][4];
        #pragma unroll
        for (int nf = 0; nf < 8; nf++) {
            #pragma unroll
            for (int e = 0; e < 4; e++) {
                S[nf][e] = 0.0f;
            }
        }
        #pragma unroll
        for (int nf = 0; nf < 8; nf++) {
            uint32_t bh[4][2];
            uint32_t bl[4][2];
            #pragma unroll
            for (int kf = 0; kf < 4; kf++) {
                const uint32_t a = kb + (uint32_t)(nf * 8 * SROWB + kf * 32) + bqoff;
                ldsm_x2(bh[kf], a);
                ldsm_x2(bl[kf], a + ATILEB);
            }
            #pragma unroll
            for (int kf = 0; kf < 4; kf++) {
                mma16816(S[nf], qh[kf], bh[kf]);
                mma16816(S[nf], qh[kf], bl[kf]);
                mma16816(S[nf], ql[kf], bh[kf]);
            }
        }

        uint32_t ph[4][4];
        uint32_t pl[4][4];
        #pragma unroll
        for (int nf = 0; nf < 8; nf++) {
            float p0 = __expf(S[nf][0] * 0.125f);
            float p1 = __expf(S[nf][1] * 0.125f);
            float p2 = __expf(S[nf][2] * 0.125f);
            float p3 = __expf(S[nf][3] * 0.125f);
            sum0 += p0 + p1;
            sum1 += p2 + p3;
            const int kf2 = nf >> 1;
            const int o   = (nf & 1) * 2;
            split2(p0, p1, &ph[kf2][o],     &pl[kf2][o]);
            split2(p2, p3, &ph[kf2][o + 1], &pl[kf2][o + 1]);
        }

        #pragma unroll
        for (int nf = 0; nf < 8; nf++) {
            #pragma unroll
            for (int kf = 0; kf < 4; kf++) {
                uint32_t vh2[2];
                uint32_t vl2[2];
                const uint32_t a = kb + 2 * ATILEB +
                                   (uint32_t)(kf * 16 * SROWB + nf * 16) + bvoff;
                ldsm_x2t(vh2, a);
                ldsm_x2t(vl2, a + ATILEB);
                mma16816(O[nf], ph[kf], vh2);
                mma16816(O[nf], ph[kf], vl2);
                mma16816(O[nf], pl[kf], vh2);
            }
        }
        __syncthreads();
    }

    sum0 += __shfl_xor_sync(0xffffffffu, sum0, 1);
    sum0 += __shfl_xor_sync(0xffffffffu, sum0, 2);
    sum1 += __shfl_xor_sync(0xffffffffu, sum1, 1);
    sum1 += __shfl_xor_sync(0xffffffffu, sum1, 2);
    const float inv0 = 1.0f / sum0;
    const float inv1 = 1.0f / sum1;

    const size_t r0 = (size_t)(qrow0 + l4) * EDIM;
    const size_t r1 = r0 + (size_t)8 * EDIM;
    #pragma unroll
    for (int nf = 0; nf < 8; nf++) {
        const int col = h * 64 + nf * 8 + l2;
        float2 w0;
        float2 w1;
        w0.x = O[nf][0] * inv0;
        w0.y = O[nf][1] * inv0;
        w1.x = O[nf][2] * inv1;
        w1.y = O[nf][3] * inv1;
        *(float2*)(yf + r0 + col) = w0;
        *(float2*)(yf + r1 + col) = w1;
    }
}

// ---------------------------------------------------------------------------
extern "C" void kernel_launch(void* const* d_in, const int* in_sizes, int n_in,
                              void* d_out, int out_size)
{
    const float* x  = (const float*)d_in[0];
    const float* Wq = (const float*)d_in[1];
    const float* bq = (const float*)d_in[2];
    const float* Wk = (const float*)d_in[3];
    const float* bk = (const float*)d_in[4];
    const float* Wv = (const float*)d_in[5];
    const float* bv = (const float*)d_in[6];
    const float* Wo = (const float*)d_in[7];
    float* out = (float*)d_out;

    float *q = 0, *k = 0, *yf = 0, *sx = 0, *sy = 0, *sw = 0;
    int8_t *x1 = 0, *x2 = 0, *y1 = 0, *y2 = 0, *w1 = 0, *w2 = 0;
    __nv_bfloat16 *qhi = 0, *qlo = 0, *khi = 0, *klo = 0, *vhi = 0, *vlo = 0;
    cudaGetSymbolAddress((void**)&q,   g_q);
    cudaGetSymbolAddress((void**)&k,   g_k);
    cudaGetSymbolAddress((void**)&yf,  g_yf);
    cudaGetSymbolAddress((void**)&x1,  g_x1);
    cudaGetSymbolAddress((void**)&x2,  g_x2);
    cudaGetSymbolAddress((void**)&y1,  g_y1);
    cudaGetSymbolAddress((void**)&y2,  g_y2);
    cudaGetSymbolAddress((void**)&sx,  g_sx);
    cudaGetSymbolAddress((void**)&sy,  g_sy);
    cudaGetSymbolAddress((void**)&w1,  g_w1);
    cudaGetSymbolAddress((void**)&w2,  g_w2);
    cudaGetSymbolAddress((void**)&sw,  g_sw);
    cudaGetSymbolAddress((void**)&qhi, g_qhi);
    cudaGetSymbolAddress((void**)&qlo, g_qlo);
    cudaGetSymbolAddress((void**)&khi, g_khi);
    cudaGetSymbolAddress((void**)&klo, g_klo);
    cudaGetSymbolAddress((void**)&vhi, g_vhi);
    cudaGetSymbolAddress((void**)&vlo, g_vlo);

    cudaFuncSetAttribute(gemm_i8, cudaFuncAttributeMaxDynamicSharedMemorySize, GEMM_SMEM);
    cudaFuncSetAttribute(attn_mma, cudaFuncAttributeMaxDynamicSharedMemorySize, ATTN_SMEM);

    quant_rows<<<M_ROWS / 8, 256>>>(x, x1, x2, sx);
    wquantT<<<EDIM / 8, 256>>>(Wq, w1 + 0 * WSZ, w2 + 0 * WSZ, sw + 0 * EDIM);
    wquantT<<<EDIM / 8, 256>>>(Wk, w1 + 1 * WSZ, w2 + 1 * WSZ, sw + 1 * EDIM);
    wquantT<<<EDIM / 8, 256>>>(Wv, w1 + 2 * WSZ, w2 + 2 * WSZ, sw + 2 * EDIM);
    wquantT<<<EDIM / 8, 256>>>(Wo, w1 + 3 * WSZ, w2 + 3 * WSZ, sw + 3 * EDIM);

    dim3 gg(EDIM / 128, M_ROWS / 128);

    gemm_i8<<<gg, 256, GEMM_SMEM>>>(x1, x2, sx, w1 + 0 * WSZ, w2 + 0 * WSZ, sw + 0 * EDIM, bq,
                                    q, (__nv_bfloat16*)0, (__nv_bfloat16*)0, M_ROWS, EDIM, EDIM);
    gemm_i8<<<gg, 256, GEMM_SMEM>>>(x1, x2, sx, w1 + 1 * WSZ, w2 + 1 * WSZ, sw + 1 * EDIM, bk,
                                    k, (__nv_bfloat16*)0, (__nv_bfloat16*)0, M_ROWS, EDIM, EDIM);
    gemm_i8<<<gg, 256, GEMM_SMEM>>>(x1, x2, sx, w1 + 2 * WSZ, w2 + 2 * WSZ, sw + 2 * EDIM, bv,
                                    (float*)0, vhi, vlo, M_ROWS, EDIM, EDIM);

    rope_split_kernel<<<dim3(49152, 2), 256>>>(q, k, qhi, qlo, khi, klo);

    attn_mma<<<dim3(BT, NHEAD * 2), 256, ATTN_SMEM>>>(qhi, qlo, khi, klo, vhi, vlo, yf);

    quant_rows<<<M_ROWS / 8, 256>>>(yf, y1, y2, sy);

    gemm_i8<<<gg, 256, GEMM_SMEM>>>(y1, y2, sy, w1 + 3 * WSZ, w2 + 3 * WSZ, sw + 3 * EDIM, (const float*)0,
                                    out, (__nv_bfloat16*)0, (__nv_bfloat16*)0, M_ROWS, EDIM, EDIM);
}

// round 9
// speedup vs baseline: 2.4462x; 2.4462x over previous
#include <cuda_runtime.h>
#include <cuda_bf16.h>
#include <cuda_fp16.h>
#include <cstdint>
#include <math.h>

// Problem constants
#define M_ROWS 32768
#define EDIM   768
#define NHEAD  12
#define HDIM   64
#define PDIM   256
#define BT     128
#define WSZ    (EDIM * EDIM)

// Scratch (allocation-free rule: __device__ globals)
__device__ __half g_xh[M_ROWS * EDIM];
__device__ __half g_xl[M_ROWS * EDIM];
__device__ __half g_yh[M_ROWS * EDIM];
__device__ __half g_yl[M_ROWS * EDIM];
__device__ __half g_wt[4 * WSZ];
__device__ __nv_bfloat16 g_qhi[M_ROWS * EDIM];
__device__ __nv_bfloat16 g_qlo[M_ROWS * EDIM];
__device__ __nv_bfloat16 g_khi[M_ROWS * EDIM];
__device__ __nv_bfloat16 g_klo[M_ROWS * EDIM];
__device__ __nv_bfloat16 g_vhi[M_ROWS * EDIM];
__device__ __nv_bfloat16 g_vlo[M_ROWS * EDIM];

// ---------------------------------------------------------------------------
// helpers
// ---------------------------------------------------------------------------
__device__ __forceinline__ uint32_t smem_u32(const void* p)
{
    uint32_t a;
    asm("{ .reg .u64 t; cvta.to.shared.u64 t, %1; cvt.u32.u64 %0, t; }"
        : "=r"(a) : "l"(p));
    return a;
}

__device__ __forceinline__ void ldsm_x4(uint32_t* r, uint32_t addr)
{
    asm volatile("ldmatrix.sync.aligned.m8n8.x4.shared.b16 {%0,%1,%2,%3}, [%4];"
        : "=r"(r[0]), "=r"(r[1]), "=r"(r[2]), "=r"(r[3]) : "r"(addr));
}

__device__ __forceinline__ void ldsm_x2(uint32_t* r, uint32_t addr)
{
    asm volatile("ldmatrix.sync.aligned.m8n8.x2.shared.b16 {%0,%1}, [%2];"
        : "=r"(r[0]), "=r"(r[1]) : "r"(addr));
}

__device__ __forceinline__ void ldsm_x2t(uint32_t* r, uint32_t addr)
{
    asm volatile("ldmatrix.sync.aligned.m8n8.x2.trans.shared.b16 {%0,%1}, [%2];"
        : "=r"(r[0]), "=r"(r[1]) : "r"(addr));
}

// bf16 mma (attention)
__device__ __forceinline__ void mma16816(float* c, const uint32_t* a, const uint32_t* b)
{
    asm volatile("mma.sync.aligned.m16n8k16.row.col.f32.bf16.bf16.f32 "
        "{%0,%1,%2,%3},{%4,%5,%6,%7},{%8,%9},{%0,%1,%2,%3};"
        : "+f"(c[0]), "+f"(c[1]), "+f"(c[2]), "+f"(c[3])
        : "r"(a[0]), "r"(a[1]), "r"(a[2]), "r"(a[3]), "r"(b[0]), "r"(b[1]));
}

// fp16 mma (GEMMs)
__device__ __forceinline__ void mma16816h(float* c, const uint32_t* a, const uint32_t* b)
{
    asm volatile("mma.sync.aligned.m16n8k16.row.col.f32.f16.f16.f32 "
        "{%0,%1,%2,%3},{%4,%5,%6,%7},{%8,%9},{%0,%1,%2,%3};"
        : "+f"(c[0]), "+f"(c[1]), "+f"(c[2]), "+f"(c[3])
        : "r"(a[0]), "r"(a[1]), "r"(a[2]), "r"(a[3]), "r"(b[0]), "r"(b[1]));
}

__device__ __forceinline__ void cp16(uint32_t saddr, const void* g)
{
    asm volatile("cp.async.cg.shared.global [%0], [%1], 16;"
        :: "r"(saddr), "l"(g) : "memory");
}
#define CP_COMMIT() asm volatile("cp.async.commit_group;" ::: "memory")
#define CP_WAIT1()  asm volatile("cp.async.wait_group 1;" ::: "memory")
#define CP_WAIT0()  asm volatile("cp.async.wait_group 0;" ::: "memory")

__device__ __forceinline__ uint32_t pack2(float x, float y)
{
    __nv_bfloat16 h0 = __float2bfloat16(x);
    __nv_bfloat16 h1 = __float2bfloat16(y);
    return (uint32_t)__bfloat16_as_ushort(h0) | ((uint32_t)__bfloat16_as_ushort(h1) << 16);
}

// split pair into bf16 hi/lo packed words
__device__ __forceinline__ void split2(float a, float b, uint32_t* hi, uint32_t* lo)
{
    __nv_bfloat16 ha = __float2bfloat16(a);
    __nv_bfloat16 hb = __float2bfloat16(b);
    *hi = (uint32_t)__bfloat16_as_ushort(ha) | ((uint32_t)__bfloat16_as_ushort(hb) << 16);
    *lo = pack2(a - __bfloat162float(ha), b - __bfloat162float(hb));
}

// split pair into fp16 hi/lo packed words
__device__ __forceinline__ void split2h(float a, float b, uint32_t* hi, uint32_t* lo)
{
    __half ha = __float2half_rn(a);
    __half hb = __float2half_rn(b);
    *hi = (uint32_t)__half_as_ushort(ha) | ((uint32_t)__half_as_ushort(hb) << 16);
    __half la = __float2half_rn(a - __half2float(ha));
    __half lb = __float2half_rn(b - __half2float(hb));
    *lo = (uint32_t)__half_as_ushort(la) | ((uint32_t)__half_as_ushort(lb) << 16);
}

// ---------------------------------------------------------------------------
// split fp32 -> fp16 hi/lo (same layout)
// ---------------------------------------------------------------------------
__global__ void split_f16(const float* __restrict__ in,
                          __half* __restrict__ hi, __half* __restrict__ lo)
{
    const int i = blockIdx.x * blockDim.x + threadIdx.x;
    float4 v = ((const float4*)in)[i];
    uint32_t h0, l0, h1, l1;
    split2h(v.x, v.y, &h0, &l0);
    split2h(v.z, v.w, &h1, &l1);
    uint2 ho; ho.x = h0; ho.y = h1;
    uint2 lw; lw.x = l0; lw.y = l1;
    ((uint2*)hi)[i] = ho;
    ((uint2*)lo)[i] = lw;
}

// transpose weights: W[K][N] -> WT[N][K] fp16
__global__ void whalfT(const float* __restrict__ W, __half* __restrict__ Wt)
{
    const int id = blockIdx.x * blockDim.x + threadIdx.x;
    const int n = id / EDIM;
    const int k = id % EDIM;
    Wt[id] = __float2half_rn(W[k * EDIM + n]);
}

// ---------------------------------------------------------------------------
// fp16 2-product GEMM: C = (Ah+Al) @ B^T_layout (+bias).
// Wt holds B transposed [N][K], single fp16. cp.async double buffered.
// mode 0: fp32 C.  mode 1: bf16 split (Chi/Clo).  mode 2: rope + bf16 split.
// ---------------------------------------------------------------------------
#define ASTR   40
#define TBYTES (128 * ASTR * 2)          // 10240
#define GEMM_SMEM (2 * 3 * TBYTES)       // 61440

__global__ __launch_bounds__(256, 1) void gemm_f16(
    const __half* __restrict__ Ah, const __half* __restrict__ Al,
    const __half* __restrict__ Wt,
    const float* __restrict__ bias, int mode, float* __restrict__ C,
    __nv_bfloat16* __restrict__ Chi, __nv_bfloat16* __restrict__ Clo,
    int M, int N, int K)
{
    extern __shared__ char sm[];

    const int tid  = threadIdx.x;
    const int bm   = blockIdx.y * 128;
    const int bn   = blockIdx.x * 128;
    const int warp = tid >> 5;
    const int lane = tid & 31;
    const int wm   = warp >> 2;
    const int wn   = warp & 3;

    const int r  = tid >> 1;
    const int ch = (tid & 1) * 16;

    const __half* gAh = Ah + (size_t)(bm + r) * K + ch;
    const __half* gAl = Al + (size_t)(bm + r) * K + ch;
    const __half* gB  = Wt + (size_t)(bn + r) * K + ch;

    const uint32_t sb     = smem_u32(sm);
    const uint32_t st_off = (uint32_t)((r * ASTR + ch) * 2);

    const int lane15 = lane & 15;
    const uint32_t aoff = (uint32_t)((wm * 64 + lane15) * 80 + (lane >> 4) * 16);
    const uint32_t boff = (uint32_t)((wn * 32 + (lane15 & 7)) * 80 + ((lane15 >> 3) & 1) * 16);

    float acc[4][4][4];
    #pragma unroll
    for (int i = 0; i < 4; i++) {
        #pragma unroll
        for (int j = 0; j < 4; j++) {
            #pragma unroll
            for (int e = 0; e < 4; e++) {
                acc[i][j][e] = 0.0f;
            }
        }
    }

    const int NIT = K / 32;   // 24

    {
        const uint32_t base = sb + st_off;
        cp16(base + 0 * TBYTES,      gAh);
        cp16(base + 0 * TBYTES + 16, gAh + 8);
        cp16(base + 1 * TBYTES,      gAl);
        cp16(base + 1 * TBYTES + 16, gAl + 8);
        cp16(base + 2 * TBYTES,      gB);
        cp16(base + 2 * TBYTES + 16, gB + 8);
        CP_COMMIT();
    }

    for (int it = 0; it < NIT; it++) {
        const int s = it & 1;

        if (it + 1 < NIT) {
            const int kt = (it + 1) * 32;
            const uint32_t base = sb + (uint32_t)((s ^ 1) * 3) * TBYTES + st_off;
            cp16(base + 0 * TBYTES,      gAh + kt);
            cp16(base + 0 * TBYTES + 16, gAh + kt + 8);
            cp16(base + 1 * TBYTES,      gAl + kt);
            cp16(base + 1 * TBYTES + 16, gAl + kt + 8);
            cp16(base + 2 * TBYTES,      gB + kt);
            cp16(base + 2 * TBYTES + 16, gB + kt + 8);
            CP_COMMIT();
            CP_WAIT1();
        } else {
            CP_WAIT0();
        }
        __syncthreads();

        const uint32_t baAh = sb + (uint32_t)(s * 3 + 0) * TBYTES;
        const uint32_t baAl = sb + (uint32_t)(s * 3 + 1) * TBYTES;
        const uint32_t baB  = sb + (uint32_t)(s * 3 + 2) * TBYTES;

        #pragma unroll
        for (int ks = 0; ks < 2; ks++) {
            const uint32_t kb = (uint32_t)(ks * 32);
            uint32_t ah[4][4];
            uint32_t al[4][4];
            uint32_t bf[4][2];
            #pragma unroll
            for (int mf = 0; mf < 4; mf++) {
                ldsm_x4(ah[mf], baAh + aoff + mf * 1280 + kb);
                ldsm_x4(al[mf], baAl + aoff + mf * 1280 + kb);
            }
            #pragma unroll
            for (int nf = 0; nf < 4; nf++) {
                ldsm_x2(bf[nf], baB + boff + nf * 640 + kb);
            }
            #pragma unroll
            for (int mf = 0; mf < 4; mf++) {
                #pragma unroll
                for (int nf = 0; nf < 4; nf++) {
                    mma16816h(acc[mf][nf], ah[mf], bf[nf]);
                    mma16816h(acc[mf][nf], al[mf], bf[nf]);
                }
            }
        }
        __syncthreads();
    }

    const int rbase = bm + wm * 64 + (lane >> 2);
    const int cbase = bn + wn * 32 + (lane & 3) * 2;
    #pragma unroll
    for (int nf = 0; nf < 4; nf++) {
        const int col = cbase + nf * 8;
        float bb0 = 0.0f;
        float bb1 = 0.0f;
        if (bias != 0) {
            bb0 = bias[col];
            bb1 = bias[col + 1];
        }
        // rope frequency for this column pair (mode 2)
        const int hd = col & 63;
        const int pr = hd >> 1;
        const int jf = pr & 15;
        const float invf = __expf(-0.57564627324851142f * (float)jf);

        #pragma unroll
        for (int mf = 0; mf < 4; mf++) {
            const int row = rbase + mf * 16;
            float a0 = acc[mf][nf][0] + bb0;
            float a1 = acc[mf][nf][1] + bb1;
            float a2 = acc[mf][nf][2] + bb0;
            float a3 = acc[mf][nf][3] + bb1;

            if (mode == 2) {
                const int p0 = row & 255;
                const int p8 = (row + 8) & 255;
                const float pos0 = (pr < 16) ? (float)(p0 & 15) : (float)(p0 >> 4);
                const float pos8 = (pr < 16) ? (float)(p8 & 15) : (float)(p8 >> 4);
                float s0, c0, s8, c8;
                sincosf(pos0 * invf, &s0, &c0);
                sincosf(pos8 * invf, &s8, &c8);
                const float r0 = a0 * c0 - a1 * s0;
                const float r1 = a1 * c0 + a0 * s0;
                const float r2 = a2 * c8 - a3 * s8;
                const float r3 = a3 * c8 + a2 * s8;
                a0 = r0; a1 = r1; a2 = r2; a3 = r3;
            }

            if (mode >= 1) {
                uint32_t h0, l0, h1, l1;
                split2(a0, a1, &h0, &l0);
                split2(a2, a3, &h1, &l1);
                *(uint32_t*)(Chi + (size_t)row * N + col)       = h0;
                *(uint32_t*)(Clo + (size_t)row * N + col)       = l0;
                *(uint32_t*)(Chi + (size_t)(row + 8) * N + col) = h1;
                *(uint32_t*)(Clo + (size_t)(row + 8) * N + col) = l1;
            } else {
                float2 v0;
                float2 v1;
                v0.x = a0; v0.y = a1;
                v1.x = a2; v1.y = a3;
                *(float2*)(C + (size_t)row * N + col)       = v0;
                *(float2*)(C + (size_t)(row + 8) * N + col) = v1;
            }
        }
    }
}

// ---------------------------------------------------------------------------
// Tensor-core attention (bf16 hi/lo 3-product, unchanged math from R6).
// Writes y as fp16 hi/lo for the output GEMM.
// ---------------------------------------------------------------------------
#define SROWB   144
#define ATILEB  (64 * SROWB)
#define ASTGB   (4 * ATILEB)
#define ATTN_SMEM (2 * ASTGB)

__global__ __launch_bounds__(256, 1) void attn_mma(
    const __nv_bfloat16* __restrict__ qhi, const __nv_bfloat16* __restrict__ qlo,
    const __nv_bfloat16* __restrict__ khi, const __nv_bfloat16* __restrict__ klo,
    const __nv_bfloat16* __restrict__ vhi, const __nv_bfloat16* __restrict__ vlo,
    __half* __restrict__ yh, __half* __restrict__ yl)
{
    extern __shared__ char sm[];

    const int tid   = threadIdx.x;
    const int warp  = tid >> 5;
    const int lane  = tid & 31;
    const int l4    = lane >> 2;
    const int l2    = (lane & 3) * 2;
    const int lane15 = lane & 15;

    const int bt   = blockIdx.x;
    const int h    = blockIdx.y >> 1;
    const int half = blockIdx.y & 1;

    const int qrow0 = bt * 256 + half * 128 + warp * 16;
    const uint32_t sb = smem_u32(sm);

    uint32_t qh[4][4];
    uint32_t ql[4][4];
    {
        const size_t qb = (size_t)(qrow0 + l4) * EDIM + h * 64;
        #pragma unroll
        for (int kf = 0; kf < 4; kf++) {
            const int c = kf * 16 + l2;
            qh[kf][0] = *(const uint32_t*)(qhi + qb + c);
            qh[kf][1] = *(const uint32_t*)(qhi + qb + (size_t)8 * EDIM + c);
            qh[kf][2] = *(const uint32_t*)(qhi + qb + c + 8);
            qh[kf][3] = *(const uint32_t*)(qhi + qb + (size_t)8 * EDIM + c + 8);
            ql[kf][0] = *(const uint32_t*)(qlo + qb + c);
            ql[kf][1] = *(const uint32_t*)(qlo + qb + (size_t)8 * EDIM + c);
            ql[kf][2] = *(const uint32_t*)(qlo + qb + c + 8);
            ql[kf][3] = *(const uint32_t*)(qlo + qb + (size_t)8 * EDIM + c + 8);
        }
    }

    float O[8][4];
    #pragma unroll
    for (int nf = 0; nf < 8; nf++) {
        #pragma unroll
        for (int e = 0; e < 4; e++) {
            O[nf][e] = 0.0f;
        }
    }
    float sum0 = 0.0f;
    float sum1 = 0.0f;

    const int lrow0 = tid >> 3;
    const int lseg0 = tid & 7;
    const int lrow1 = (tid + 256) >> 3;
    const int lseg1 = tid & 7;

    #define ATTN_LOAD(c, s) do {                                                   \
        const int jg0 = bt * 256 + (c) * 64;                                        \
        const uint32_t base = sb + (uint32_t)(s) * ASTGB;                           \
        size_t g0 = (size_t)(jg0 + lrow0) * EDIM + h * 64 + lseg0 * 8;              \
        uint32_t d0 = base + (uint32_t)(lrow0 * SROWB + lseg0 * 16);                \
        cp16(d0 + 0 * ATILEB, khi + g0);                                            \
        cp16(d0 + 1 * ATILEB, klo + g0);                                            \
        cp16(d0 + 2 * ATILEB, vhi + g0);                                            \
        cp16(d0 + 3 * ATILEB, vlo + g0);                                            \
        size_t g1 = (size_t)(jg0 + lrow1) * EDIM + h * 64 + lseg1 * 8;              \
        uint32_t d1 = base + (uint32_t)(lrow1 * SROWB + lseg1 * 16);                \
        cp16(d1 + 0 * ATILEB, khi + g1);                                            \
        cp16(d1 + 1 * ATILEB, klo + g1);                                            \
        cp16(d1 + 2 * ATILEB, vhi + g1);                                            \
        cp16(d1 + 3 * ATILEB, vlo + g1);                                            \
        CP_COMMIT();                                                                \
    } while (0)

    ATTN_LOAD(0, 0);

    const uint32_t bqoff = (uint32_t)((lane15 & 7) * SROWB + ((lane15 >> 3) & 1) * 16);
    const uint32_t bvoff = (uint32_t)(lane15 * SROWB);

    for (int c = 0; c < 4; c++) {
        const int s = c & 1;
        if (c < 3) {
            ATTN_LOAD(c + 1, s ^ 1);
            CP_WAIT1();
        } else {
            CP_WAIT0();
        }
        __syncthreads();

        const uint32_t kb = sb + (uint32_t)s * ASTGB;

        float S[8][4];
        #pragma unroll
        for (int nf = 0; nf < 8; nf++) {
            #pragma unroll
            for (int e = 0; e < 4; e++) {
                S[nf][e] = 0.0f;
            }
        }
        #pragma unroll
        for (int nf = 0; nf < 8; nf++) {
            uint32_t bh[4][2];
            uint32_t bl[4][2];
            #pragma unroll
            for (int kf = 0; kf < 4; kf++) {
                const uint32_t a = kb + (uint32_t)(nf * 8 * SROWB + kf * 32) + bqoff;
                ldsm_x2(bh[kf], a);
                ldsm_x2(bl[kf], a + ATILEB);
            }
            #pragma unroll
            for (int kf = 0; kf < 4; kf++) {
                mma16816(S[nf], qh[kf], bh[kf]);
                mma16816(S[nf], qh[kf], bl[kf]);
                mma16816(S[nf], ql[kf], bh[kf]);
            }
        }

        uint32_t ph[4][4];
        uint32_t pl[4][4];
        #pragma unroll
        for (int nf = 0; nf < 8; nf++) {
            float p0 = __expf(S[nf][0] * 0.125f);
            float p1 = __expf(S[nf][1] * 0.125f);
            float p2 = __expf(S[nf][2] * 0.125f);
            float p3 = __expf(S[nf][3] * 0.125f);
            sum0 += p0 + p1;
            sum1 += p2 + p3;
            const int kf2 = nf >> 1;
            const int o   = (nf & 1) * 2;
            split2(p0, p1, &ph[kf2][o],     &pl[kf2][o]);
            split2(p2, p3, &ph[kf2][o + 1], &pl[kf2][o + 1]);
        }

        #pragma unroll
        for (int nf = 0; nf < 8; nf++) {
            #pragma unroll
            for (int kf = 0; kf < 4; kf++) {
                uint32_t vh2[2];
                uint32_t vl2[2];
                const uint32_t a = kb + 2 * ATILEB +
                                   (uint32_t)(kf * 16 * SROWB + nf * 16) + bvoff;
                ldsm_x2t(vh2, a);
                ldsm_x2t(vl2, a + ATILEB);
                mma16816(O[nf], ph[kf], vh2);
                mma16816(O[nf], ph[kf], vl2);
                mma16816(O[nf], pl[kf], vh2);
            }
        }
        __syncthreads();
    }

    sum0 += __shfl_xor_sync(0xffffffffu, sum0, 1);
    sum0 += __shfl_xor_sync(0xffffffffu, sum0, 2);
    sum1 += __shfl_xor_sync(0xffffffffu, sum1, 1);
    sum1 += __shfl_xor_sync(0xffffffffu, sum1, 2);
    const float inv0 = 1.0f / sum0;
    const float inv1 = 1.0f / sum1;

    const size_t r0 = (size_t)(qrow0 + l4) * EDIM;
    const size_t r1 = r0 + (size_t)8 * EDIM;
    #pragma unroll
    for (int nf = 0; nf < 8; nf++) {
        const int col = h * 64 + nf * 8 + l2;
        uint32_t hw, lw;
        split2h(O[nf][0] * inv0, O[nf][1] * inv0, &hw, &lw);
        *(uint32_t*)(yh + r0 + col) = hw;
        *(uint32_t*)(yl + r0 + col) = lw;
        split2h(O[nf][2] * inv1, O[nf][3] * inv1, &hw, &lw);
        *(uint32_t*)(yh + r1 + col) = hw;
        *(uint32_t*)(yl + r1 + col) = lw;
    }
}

// ---------------------------------------------------------------------------
extern "C" void kernel_launch(void* const* d_in, const int* in_sizes, int n_in,
                              void* d_out, int out_size)
{
    const float* x  = (const float*)d_in[0];
    const float* Wq = (const float*)d_in[1];
    const float* bq = (const float*)d_in[2];
    const float* Wk = (const float*)d_in[3];
    const float* bk = (const float*)d_in[4];
    const float* Wv = (const float*)d_in[5];
    const float* bv = (const float*)d_in[6];
    const float* Wo = (const float*)d_in[7];
    float* out = (float*)d_out;

    __half *xh = 0, *xl = 0, *yh = 0, *yl = 0, *wt = 0;
    __nv_bfloat16 *qhi = 0, *qlo = 0, *khi = 0, *klo = 0, *vhi = 0, *vlo = 0;
    cudaGetSymbolAddress((void**)&xh,  g_xh);
    cudaGetSymbolAddress((void**)&xl,  g_xl);
    cudaGetSymbolAddress((void**)&yh,  g_yh);
    cudaGetSymbolAddress((void**)&yl,  g_yl);
    cudaGetSymbolAddress((void**)&wt,  g_wt);
    cudaGetSymbolAddress((void**)&qhi, g_qhi);
    cudaGetSymbolAddress((void**)&qlo, g_qlo);
    cudaGetSymbolAddress((void**)&khi, g_khi);
    cudaGetSymbolAddress((void**)&klo, g_klo);
    cudaGetSymbolAddress((void**)&vhi, g_vhi);
    cudaGetSymbolAddress((void**)&vlo, g_vlo);

    cudaFuncSetAttribute(gemm_f16, cudaFuncAttributeMaxDynamicSharedMemorySize, GEMM_SMEM);
    cudaFuncSetAttribute(attn_mma, cudaFuncAttributeMaxDynamicSharedMemorySize, ATTN_SMEM);

    split_f16<<<(M_ROWS * EDIM / 4) / 256, 256>>>(x, xh, xl);
    whalfT<<<WSZ / 256, 256>>>(Wq, wt + 0 * WSZ);
    whalfT<<<WSZ / 256, 256>>>(Wk, wt + 1 * WSZ);
    whalfT<<<WSZ / 256, 256>>>(Wv, wt + 2 * WSZ);
    whalfT<<<WSZ / 256, 256>>>(Wo, wt + 3 * WSZ);

    dim3 gg(EDIM / 128, M_ROWS / 128);

    // Q: GEMM + bias + rope -> bf16 split
    gemm_f16<<<gg, 256, GEMM_SMEM>>>(xh, xl, wt + 0 * WSZ, bq, 2,
                                     (float*)0, qhi, qlo, M_ROWS, EDIM, EDIM);
    // K: GEMM + bias + rope -> bf16 split
    gemm_f16<<<gg, 256, GEMM_SMEM>>>(xh, xl, wt + 1 * WSZ, bk, 2,
                                     (float*)0, khi, klo, M_ROWS, EDIM, EDIM);
    // V: GEMM + bias -> bf16 split
    gemm_f16<<<gg, 256, GEMM_SMEM>>>(xh, xl, wt + 2 * WSZ, bv, 1,
                                     (float*)0, vhi, vlo, M_ROWS, EDIM, EDIM);

    attn_mma<<<dim3(BT, NHEAD * 2), 256, ATTN_SMEM>>>(qhi, qlo, khi, klo, vhi, vlo, yh, yl);

    // output GEMM -> fp32
    gemm_f16<<<gg, 256, GEMM_SMEM>>>(yh, yl, wt + 3 * WSZ, (const float*)0, 0,
                                     out, (__nv_bfloat16*)0, (__nv_bfloat16*)0, M_ROWS, EDIM, EDIM);
}

// round 10
// speedup vs baseline: 3.9315x; 1.6072x over previous
#include <cuda_runtime.h>
#include <cuda_bf16.h>
#include <cuda_fp16.h>
#include <cstdint>
#include <math.h>

// Problem constants
#define M_ROWS 32768
#define EDIM   768
#define NHEAD  12
#define HDIM   64
#define PDIM   256
#define BT     128
#define WSZ    (EDIM * EDIM)

// Scratch (allocation-free rule: __device__ globals)
__device__ __half g_xh[M_ROWS * EDIM];
__device__ __half g_yh[M_ROWS * EDIM];
__device__ __half g_wt[4 * WSZ];
__device__ __nv_bfloat16 g_qhi[M_ROWS * EDIM];
__device__ __nv_bfloat16 g_qlo[M_ROWS * EDIM];
__device__ __nv_bfloat16 g_khi[M_ROWS * EDIM];
__device__ __nv_bfloat16 g_klo[M_ROWS * EDIM];
__device__ __nv_bfloat16 g_vhi[M_ROWS * EDIM];
__device__ __nv_bfloat16 g_vlo[M_ROWS * EDIM];

// ---------------------------------------------------------------------------
// helpers
// ---------------------------------------------------------------------------
__device__ __forceinline__ uint32_t smem_u32(const void* p)
{
    uint32_t a;
    asm("{ .reg .u64 t; cvta.to.shared.u64 t, %1; cvt.u32.u64 %0, t; }"
        : "=r"(a) : "l"(p));
    return a;
}

__device__ __forceinline__ void ldsm_x4(uint32_t* r, uint32_t addr)
{
    asm volatile("ldmatrix.sync.aligned.m8n8.x4.shared.b16 {%0,%1,%2,%3}, [%4];"
        : "=r"(r[0]), "=r"(r[1]), "=r"(r[2]), "=r"(r[3]) : "r"(addr));
}

__device__ __forceinline__ void ldsm_x2(uint32_t* r, uint32_t addr)
{
    asm volatile("ldmatrix.sync.aligned.m8n8.x2.shared.b16 {%0,%1}, [%2];"
        : "=r"(r[0]), "=r"(r[1]) : "r"(addr));
}

__device__ __forceinline__ void ldsm_x2t(uint32_t* r, uint32_t addr)
{
    asm volatile("ldmatrix.sync.aligned.m8n8.x2.trans.shared.b16 {%0,%1}, [%2];"
        : "=r"(r[0]), "=r"(r[1]) : "r"(addr));
}

// bf16 mma (attention)
__device__ __forceinline__ void mma16816(float* c, const uint32_t* a, const uint32_t* b)
{
    asm volatile("mma.sync.aligned.m16n8k16.row.col.f32.bf16.bf16.f32 "
        "{%0,%1,%2,%3},{%4,%5,%6,%7},{%8,%9},{%0,%1,%2,%3};"
        : "+f"(c[0]), "+f"(c[1]), "+f"(c[2]), "+f"(c[3])
        : "r"(a[0]), "r"(a[1]), "r"(a[2]), "r"(a[3]), "r"(b[0]), "r"(b[1]));
}

// fp16 mma (GEMMs)
__device__ __forceinline__ void mma16816h(float* c, const uint32_t* a, const uint32_t* b)
{
    asm volatile("mma.sync.aligned.m16n8k16.row.col.f32.f16.f16.f32 "
        "{%0,%1,%2,%3},{%4,%5,%6,%7},{%8,%9},{%0,%1,%2,%3};"
        : "+f"(c[0]), "+f"(c[1]), "+f"(c[2]), "+f"(c[3])
        : "r"(a[0]), "r"(a[1]), "r"(a[2]), "r"(a[3]), "r"(b[0]), "r"(b[1]));
}

__device__ __forceinline__ void cp16(uint32_t saddr, const void* g)
{
    asm volatile("cp.async.cg.shared.global [%0], [%1], 16;"
        :: "r"(saddr), "l"(g) : "memory");
}
#define CP_COMMIT() asm volatile("cp.async.commit_group;" ::: "memory")
#define CP_WAIT1()  asm volatile("cp.async.wait_group 1;" ::: "memory")
#define CP_WAIT0()  asm volatile("cp.async.wait_group 0;" ::: "memory")

__device__ __forceinline__ uint32_t pack2(float x, float y)
{
    __nv_bfloat16 h0 = __float2bfloat16(x);
    __nv_bfloat16 h1 = __float2bfloat16(y);
    return (uint32_t)__bfloat16_as_ushort(h0) | ((uint32_t)__bfloat16_as_ushort(h1) << 16);
}

// split pair into bf16 hi/lo packed words
__device__ __forceinline__ void split2(float a, float b, uint32_t* hi, uint32_t* lo)
{
    __nv_bfloat16 ha = __float2bfloat16(a);
    __nv_bfloat16 hb = __float2bfloat16(b);
    *hi = (uint32_t)__bfloat16_as_ushort(ha) | ((uint32_t)__bfloat16_as_ushort(hb) << 16);
    *lo = pack2(a - __bfloat162float(ha), b - __bfloat162float(hb));
}

// pack pair into fp16 word
__device__ __forceinline__ uint32_t pack2h(float a, float b)
{
    __half ha = __float2half_rn(a);
    __half hb = __float2half_rn(b);
    return (uint32_t)__half_as_ushort(ha) | ((uint32_t)__half_as_ushort(hb) << 16);
}

// ---------------------------------------------------------------------------
// convert fp32 -> fp16 (same layout)
// ---------------------------------------------------------------------------
__global__ void cvt_f16(const float* __restrict__ in, __half* __restrict__ out)
{
    const int i = blockIdx.x * blockDim.x + threadIdx.x;
    float4 v = ((const float4*)in)[i];
    uint2 o;
    o.x = pack2h(v.x, v.y);
    o.y = pack2h(v.z, v.w);
    ((uint2*)out)[i] = o;
}

// transpose 4 weights at once: W[K][N] -> WT[N][K] fp16 (blockIdx.y selects)
__global__ void whalfT4(const float* __restrict__ W0, const float* __restrict__ W1,
                        const float* __restrict__ W2, const float* __restrict__ W3,
                        __half* __restrict__ Wt)
{
    const int id = blockIdx.x * blockDim.x + threadIdx.x;
    const int w  = blockIdx.y;
    const float* W = (w == 0) ? W0 : (w == 1) ? W1 : (w == 2) ? W2 : W3;
    const int n = id / EDIM;
    const int k = id % EDIM;
    Wt[(size_t)w * WSZ + id] = __float2half_rn(W[k * EDIM + n]);
}

// ---------------------------------------------------------------------------
// fp16 single-product GEMM: C = A @ B^T_layout (+bias), A and B both fp16.
// Wt holds B transposed [N][K]. cp.async double buffered.
// mode 0: fp32 C.  mode 1: bf16 split (Chi/Clo).  mode 2: rope + bf16 split.
// ---------------------------------------------------------------------------
#define ASTR   40
#define TBYTES (128 * ASTR * 2)          // 10240
#define GEMM_SMEM (2 * 2 * TBYTES)       // 40960

__global__ __launch_bounds__(256, 2) void gemm_f16(
    const __half* __restrict__ Ah, const __half* __restrict__ Wt,
    const float* __restrict__ bias, int mode, float* __restrict__ C,
    __nv_bfloat16* __restrict__ Chi, __nv_bfloat16* __restrict__ Clo,
    int M, int N, int K)
{
    extern __shared__ char sm[];

    const int tid  = threadIdx.x;
    const int bm   = blockIdx.y * 128;
    const int bn   = blockIdx.x * 128;
    const int warp = tid >> 5;
    const int lane = tid & 31;
    const int wm   = warp >> 2;
    const int wn   = warp & 3;

    const int r  = tid >> 1;
    const int ch = (tid & 1) * 16;

    const __half* gA = Ah + (size_t)(bm + r) * K + ch;
    const __half* gB = Wt + (size_t)(bn + r) * K + ch;

    const uint32_t sb     = smem_u32(sm);
    const uint32_t st_off = (uint32_t)((r * ASTR + ch) * 2);

    const int lane15 = lane & 15;
    const uint32_t aoff = (uint32_t)((wm * 64 + lane15) * 80 + (lane >> 4) * 16);
    const uint32_t boff = (uint32_t)((wn * 32 + (lane15 & 7)) * 80 + ((lane15 >> 3) & 1) * 16);

    float acc[4][4][4];
    #pragma unroll
    for (int i = 0; i < 4; i++) {
        #pragma unroll
        for (int j = 0; j < 4; j++) {
            #pragma unroll
            for (int e = 0; e < 4; e++) {
                acc[i][j][e] = 0.0f;
            }
        }
    }

    const int NIT = K / 32;   // 24

    {
        const uint32_t base = sb + st_off;
        cp16(base + 0 * TBYTES,      gA);
        cp16(base + 0 * TBYTES + 16, gA + 8);
        cp16(base + 1 * TBYTES,      gB);
        cp16(base + 1 * TBYTES + 16, gB + 8);
        CP_COMMIT();
    }

    for (int it = 0; it < NIT; it++) {
        const int s = it & 1;

        if (it + 1 < NIT) {
            const int kt = (it + 1) * 32;
            const uint32_t base = sb + (uint32_t)((s ^ 1) * 2) * TBYTES + st_off;
            cp16(base + 0 * TBYTES,      gA + kt);
            cp16(base + 0 * TBYTES + 16, gA + kt + 8);
            cp16(base + 1 * TBYTES,      gB + kt);
            cp16(base + 1 * TBYTES + 16, gB + kt + 8);
            CP_COMMIT();
            CP_WAIT1();
        } else {
            CP_WAIT0();
        }
        __syncthreads();

        const uint32_t baA = sb + (uint32_t)(s * 2 + 0) * TBYTES;
        const uint32_t baB = sb + (uint32_t)(s * 2 + 1) * TBYTES;

        #pragma unroll
        for (int ks = 0; ks < 2; ks++) {
            const uint32_t kb = (uint32_t)(ks * 32);
            uint32_t ah[4][4];
            uint32_t bf[4][2];
            #pragma unroll
            for (int mf = 0; mf < 4; mf++) {
                ldsm_x4(ah[mf], baA + aoff + mf * 1280 + kb);
            }
            #pragma unroll
            for (int nf = 0; nf < 4; nf++) {
                ldsm_x2(bf[nf], baB + boff + nf * 640 + kb);
            }
            #pragma unroll
            for (int mf = 0; mf < 4; mf++) {
                #pragma unroll
                for (int nf = 0; nf < 4; nf++) {
                    mma16816h(acc[mf][nf], ah[mf], bf[nf]);
                }
            }
        }
        __syncthreads();
    }

    const int rbase = bm + wm * 64 + (lane >> 2);
    const int cbase = bn + wn * 32 + (lane & 3) * 2;
    #pragma unroll
    for (int nf = 0; nf < 4; nf++) {
        const int col = cbase + nf * 8;
        float bb0 = 0.0f;
        float bb1 = 0.0f;
        if (bias != 0) {
            bb0 = bias[col];
            bb1 = bias[col + 1];
        }
        // rope frequency for this column pair (mode 2)
        const int hd = col & 63;
        const int pr = hd >> 1;
        const int jf = pr & 15;
        const float invf = __expf(-0.57564627324851142f * (float)jf);

        #pragma unroll
        for (int mf = 0; mf < 4; mf++) {
            const int row = rbase + mf * 16;
            float a0 = acc[mf][nf][0] + bb0;
            float a1 = acc[mf][nf][1] + bb1;
            float a2 = acc[mf][nf][2] + bb0;
            float a3 = acc[mf][nf][3] + bb1;

            if (mode == 2) {
                const int p0 = row & 255;
                const int p8 = (row + 8) & 255;
                const float pos0 = (pr < 16) ? (float)(p0 & 15) : (float)(p0 >> 4);
                const float pos8 = (pr < 16) ? (float)(p8 & 15) : (float)(p8 >> 4);
                float s0, c0, s8, c8;
                sincosf(pos0 * invf, &s0, &c0);
                sincosf(pos8 * invf, &s8, &c8);
                const float r0 = a0 * c0 - a1 * s0;
                const float r1 = a1 * c0 + a0 * s0;
                const float r2 = a2 * c8 - a3 * s8;
                const float r3 = a3 * c8 + a2 * s8;
                a0 = r0; a1 = r1; a2 = r2; a3 = r3;
            }

            if (mode >= 1) {
                uint32_t h0, l0, h1, l1;
                split2(a0, a1, &h0, &l0);
                split2(a2, a3, &h1, &l1);
                *(uint32_t*)(Chi + (size_t)row * N + col)       = h0;
                *(uint32_t*)(Clo + (size_t)row * N + col)       = l0;
                *(uint32_t*)(Chi + (size_t)(row + 8) * N + col) = h1;
                *(uint32_t*)(Clo + (size_t)(row + 8) * N + col) = l1;
            } else {
                float2 v0;
                float2 v1;
                v0.x = a0; v0.y = a1;
                v1.x = a2; v1.y = a3;
                *(float2*)(C + (size_t)row * N + col)       = v0;
                *(float2*)(C + (size_t)(row + 8) * N + col) = v1;
            }
        }
    }
}

// ---------------------------------------------------------------------------
// Tensor-core attention (bf16 hi/lo 3-product, unchanged math).
// Writes y as single fp16 for the output GEMM.
// ---------------------------------------------------------------------------
#define SROWB   144
#define ATILEB  (64 * SROWB)
#define ASTGB   (4 * ATILEB)
#define ATTN_SMEM (2 * ASTGB)

__global__ __launch_bounds__(256, 1) void attn_mma(
    const __nv_bfloat16* __restrict__ qhi, const __nv_bfloat16* __restrict__ qlo,
    const __nv_bfloat16* __restrict__ khi, const __nv_bfloat16* __restrict__ klo,
    const __nv_bfloat16* __restrict__ vhi, const __nv_bfloat16* __restrict__ vlo,
    __half* __restrict__ yh)
{
    extern __shared__ char sm[];

    const int tid   = threadIdx.x;
    const int warp  = tid >> 5;
    const int lane  = tid & 31;
    const int l4    = lane >> 2;
    const int l2    = (lane & 3) * 2;
    const int lane15 = lane & 15;

    const int bt   = blockIdx.x;
    const int h    = blockIdx.y >> 1;
    const int half = blockIdx.y & 1;

    const int qrow0 = bt * 256 + half * 128 + warp * 16;
    const uint32_t sb = smem_u32(sm);

    uint32_t qh[4][4];
    uint32_t ql[4][4];
    {
        const size_t qb = (size_t)(qrow0 + l4) * EDIM + h * 64;
        #pragma unroll
        for (int kf = 0; kf < 4; kf++) {
            const int c = kf * 16 + l2;
            qh[kf][0] = *(const uint32_t*)(qhi + qb + c);
            qh[kf][1] = *(const uint32_t*)(qhi + qb + (size_t)8 * EDIM + c);
            qh[kf][2] = *(const uint32_t*)(qhi + qb + c + 8);
            qh[kf][3] = *(const uint32_t*)(qhi + qb + (size_t)8 * EDIM + c + 8);
            ql[kf][0] = *(const uint32_t*)(qlo + qb + c);
            ql[kf][1] = *(const uint32_t*)(qlo + qb + (size_t)8 * EDIM + c);
            ql[kf][2] = *(const uint32_t*)(qlo + qb + c + 8);
            ql[kf][3] = *(const uint32_t*)(qlo + qb + (size_t)8 * EDIM + c + 8);
        }
    }

    float O[8][4];
    #pragma unroll
    for (int nf = 0; nf < 8; nf++) {
        #pragma unroll
        for (int e = 0; e < 4; e++) {
            O[nf][e] = 0.0f;
        }
    }
    float sum0 = 0.0f;
    float sum1 = 0.0f;

    const int lrow0 = tid >> 3;
    const int lseg0 = tid & 7;
    const int lrow1 = (tid + 256) >> 3;
    const int lseg1 = tid & 7;

    #define ATTN_LOAD(c, s) do {                                                   \
        const int jg0 = bt * 256 + (c) * 64;                                        \
        const uint32_t base = sb + (uint32_t)(s) * ASTGB;                           \
        size_t g0 = (size_t)(jg0 + lrow0) * EDIM + h * 64 + lseg0 * 8;              \
        uint32_t d0 = base + (uint32_t)(lrow0 * SROWB + lseg0 * 16);                \
        cp16(d0 + 0 * ATILEB, khi + g0);                                            \
        cp16(d0 + 1 * ATILEB, klo + g0);                                            \
        cp16(d0 + 2 * ATILEB, vhi + g0);                                            \
        cp16(d0 + 3 * ATILEB, vlo + g0);                                            \
        size_t g1 = (size_t)(jg0 + lrow1) * EDIM + h * 64 + lseg1 * 8;              \
        uint32_t d1 = base + (uint32_t)(lrow1 * SROWB + lseg1 * 16);                \
        cp16(d1 + 0 * ATILEB, khi + g1);                                            \
        cp16(d1 + 1 * ATILEB, klo + g1);                                            \
        cp16(d1 + 2 * ATILEB, vhi + g1);                                            \
        cp16(d1 + 3 * ATILEB, vlo + g1);                                            \
        CP_COMMIT();                                                                \
    } while (0)

    ATTN_LOAD(0, 0);

    const uint32_t bqoff = (uint32_t)((lane15 & 7) * SROWB + ((lane15 >> 3) & 1) * 16);
    const uint32_t bvoff = (uint32_t)(lane15 * SROWB);

    for (int c = 0; c < 4; c++) {
        const int s = c & 1;
        if (c < 3) {
            ATTN_LOAD(c + 1, s ^ 1);
            CP_WAIT1();
        } else {
            CP_WAIT0();
        }
        __syncthreads();

        const uint32_t kb = sb + (uint32_t)s * ASTGB;

        float S[8][4];
        #pragma unroll
        for (int nf = 0; nf < 8; nf++) {
            #pragma unroll
            for (int e = 0; e < 4; e++) {
                S[nf][e] = 0.0f;
            }
        }
        #pragma unroll
        for (int nf = 0; nf < 8; nf++) {
            uint32_t bh[4][2];
            uint32_t bl[4][2];
            #pragma unroll
            for (int kf = 0; kf < 4; kf++) {
                const uint32_t a = kb + (uint32_t)(nf * 8 * SROWB + kf * 32) + bqoff;
                ldsm_x2(bh[kf], a);
                ldsm_x2(bl[kf], a + ATILEB);
            }
            #pragma unroll
            for (int kf = 0; kf < 4; kf++) {
                mma16816(S[nf], qh[kf], bh[kf]);
                mma16816(S[nf], qh[kf], bl[kf]);
                mma16816(S[nf], ql[kf], bh[kf]);
            }
        }

        uint32_t ph[4][4];
        uint32_t pl[4][4];
        #pragma unroll
        for (int nf = 0; nf < 8; nf++) {
            float p0 = __expf(S[nf][0] * 0.125f);
            float p1 = __expf(S[nf][1] * 0.125f);
            float p2 = __expf(S[nf][2] * 0.125f);
            float p3 = __expf(S[nf][3] * 0.125f);
            sum0 += p0 + p1;
            sum1 += p2 + p3;
            const int kf2 = nf >> 1;
            const int o   = (nf & 1) * 2;
            split2(p0, p1, &ph[kf2][o],     &pl[kf2][o]);
            split2(p2, p3, &ph[kf2][o + 1], &pl[kf2][o + 1]);
        }

        #pragma unroll
        for (int nf = 0; nf < 8; nf++) {
            #pragma unroll
            for (int kf = 0; kf < 4; kf++) {
                uint32_t vh2[2];
                uint32_t vl2[2];
                const uint32_t a = kb + 2 * ATILEB +
                                   (uint32_t)(kf * 16 * SROWB + nf * 16) + bvoff;
                ldsm_x2t(vh2, a);
                ldsm_x2t(vl2, a + ATILEB);
                mma16816(O[nf], ph[kf], vh2);
                mma16816(O[nf], ph[kf], vl2);
                mma16816(O[nf], pl[kf], vh2);
            }
        }
        __syncthreads();
    }

    sum0 += __shfl_xor_sync(0xffffffffu, sum0, 1);
    sum0 += __shfl_xor_sync(0xffffffffu, sum0, 2);
    sum1 += __shfl_xor_sync(0xffffffffu, sum1, 1);
    sum1 += __shfl_xor_sync(0xffffffffu, sum1, 2);
    const float inv0 = 1.0f / sum0;
    const float inv1 = 1.0f / sum1;

    const size_t r0 = (size_t)(qrow0 + l4) * EDIM;
    const size_t r1 = r0 + (size_t)8 * EDIM;
    #pragma unroll
    for (int nf = 0; nf < 8; nf++) {
        const int col = h * 64 + nf * 8 + l2;
        *(uint32_t*)(yh + r0 + col) = pack2h(O[nf][0] * inv0, O[nf][1] * inv0);
        *(uint32_t*)(yh + r1 + col) = pack2h(O[nf][2] * inv1, O[nf][3] * inv1);
    }
}

// ---------------------------------------------------------------------------
extern "C" void kernel_launch(void* const* d_in, const int* in_sizes, int n_in,
                              void* d_out, int out_size)
{
    const float* x  = (const float*)d_in[0];
    const float* Wq = (const float*)d_in[1];
    const float* bq = (const float*)d_in[2];
    const float* Wk = (const float*)d_in[3];
    const float* bk = (const float*)d_in[4];
    const float* Wv = (const float*)d_in[5];
    const float* bv = (const float*)d_in[6];
    const float* Wo = (const float*)d_in[7];
    float* out = (float*)d_out;

    __half *xh = 0, *yh = 0, *wt = 0;
    __nv_bfloat16 *qhi = 0, *qlo = 0, *khi = 0, *klo = 0, *vhi = 0, *vlo = 0;
    cudaGetSymbolAddress((void**)&xh,  g_xh);
    cudaGetSymbolAddress((void**)&yh,  g_yh);
    cudaGetSymbolAddress((void**)&wt,  g_wt);
    cudaGetSymbolAddress((void**)&qhi, g_qhi);
    cudaGetSymbolAddress((void**)&qlo, g_qlo);
    cudaGetSymbolAddress((void**)&khi, g_khi);
    cudaGetSymbolAddress((void**)&klo, g_klo);
    cudaGetSymbolAddress((void**)&vhi, g_vhi);
    cudaGetSymbolAddress((void**)&vlo, g_vlo);

    cudaFuncSetAttribute(gemm_f16, cudaFuncAttributeMaxDynamicSharedMemorySize, GEMM_SMEM);
    cudaFuncSetAttribute(attn_mma, cudaFuncAttributeMaxDynamicSharedMemorySize, ATTN_SMEM);

    cvt_f16<<<(M_ROWS * EDIM / 4) / 256, 256>>>(x, xh);
    whalfT4<<<dim3(WSZ / 256, 4), 256>>>(Wq, Wk, Wv, Wo, wt);

    dim3 gg(EDIM / 128, M_ROWS / 128);

    // Q: GEMM + bias + rope -> bf16 split
    gemm_f16<<<gg, 256, GEMM_SMEM>>>(xh, wt + 0 * WSZ, bq, 2,
                                     (float*)0, qhi, qlo, M_ROWS, EDIM, EDIM);
    // K: GEMM + bias + rope -> bf16 split
    gemm_f16<<<gg, 256, GEMM_SMEM>>>(xh, wt + 1 * WSZ, bk, 2,
                                     (float*)0, khi, klo, M_ROWS, EDIM, EDIM);
    // V: GEMM + bias -> bf16 split
    gemm_f16<<<gg, 256, GEMM_SMEM>>>(xh, wt + 2 * WSZ, bv, 1,
                                     (float*)0, vhi, vlo, M_ROWS, EDIM, EDIM);

    attn_mma<<<dim3(BT, NHEAD * 2), 256, ATTN_SMEM>>>(qhi, qlo, khi, klo, vhi, vlo, yh);

    // output GEMM -> fp32
    gemm_f16<<<gg, 256, GEMM_SMEM>>>(yh, wt + 3 * WSZ, (const float*)0, 0,
                                     out, (__nv_bfloat16*)0, (__nv_bfloat16*)0, M_ROWS, EDIM, EDIM);
}

// round 11
// speedup vs baseline: 3.9984x; 1.0170x over previous
#include <cuda_runtime.h>
#include <cuda_bf16.h>
#include <cuda_fp16.h>
#include <cstdint>
#include <math.h>

// Problem constants
#define M_ROWS 32768
#define EDIM   768
#define NHEAD  12
#define HDIM   64
#define PDIM   256
#define BT     128
#define WSZ    (EDIM * EDIM)

// Scratch (allocation-free rule: __device__ globals)
__device__ __half g_xh[M_ROWS * EDIM];
__device__ __half g_yh[M_ROWS * EDIM];
__device__ __half g_wt[4 * WSZ];
__device__ __nv_bfloat16 g_qhi[M_ROWS * EDIM];
__device__ __nv_bfloat16 g_qlo[M_ROWS * EDIM];
__device__ __nv_bfloat16 g_khi[M_ROWS * EDIM];
__device__ __nv_bfloat16 g_klo[M_ROWS * EDIM];
__device__ __nv_bfloat16 g_vhi[M_ROWS * EDIM];
__device__ __nv_bfloat16 g_vlo[M_ROWS * EDIM];

// ---------------------------------------------------------------------------
// helpers
// ---------------------------------------------------------------------------
__device__ __forceinline__ uint32_t smem_u32(const void* p)
{
    uint32_t a;
    asm("{ .reg .u64 t; cvta.to.shared.u64 t, %1; cvt.u32.u64 %0, t; }"
        : "=r"(a) : "l"(p));
    return a;
}

__device__ __forceinline__ void ldsm_x4(uint32_t* r, uint32_t addr)
{
    asm volatile("ldmatrix.sync.aligned.m8n8.x4.shared.b16 {%0,%1,%2,%3}, [%4];"
        : "=r"(r[0]), "=r"(r[1]), "=r"(r[2]), "=r"(r[3]) : "r"(addr));
}

__device__ __forceinline__ void ldsm_x2(uint32_t* r, uint32_t addr)
{
    asm volatile("ldmatrix.sync.aligned.m8n8.x2.shared.b16 {%0,%1}, [%2];"
        : "=r"(r[0]), "=r"(r[1]) : "r"(addr));
}

__device__ __forceinline__ void ldsm_x2t(uint32_t* r, uint32_t addr)
{
    asm volatile("ldmatrix.sync.aligned.m8n8.x2.trans.shared.b16 {%0,%1}, [%2];"
        : "=r"(r[0]), "=r"(r[1]) : "r"(addr));
}

// bf16 mma (attention)
__device__ __forceinline__ void mma16816(float* c, const uint32_t* a, const uint32_t* b)
{
    asm volatile("mma.sync.aligned.m16n8k16.row.col.f32.bf16.bf16.f32 "
        "{%0,%1,%2,%3},{%4,%5,%6,%7},{%8,%9},{%0,%1,%2,%3};"
        : "+f"(c[0]), "+f"(c[1]), "+f"(c[2]), "+f"(c[3])
        : "r"(a[0]), "r"(a[1]), "r"(a[2]), "r"(a[3]), "r"(b[0]), "r"(b[1]));
}

// fp16 mma (GEMMs)
__device__ __forceinline__ void mma16816h(float* c, const uint32_t* a, const uint32_t* b)
{
    asm volatile("mma.sync.aligned.m16n8k16.row.col.f32.f16.f16.f32 "
        "{%0,%1,%2,%3},{%4,%5,%6,%7},{%8,%9},{%0,%1,%2,%3};"
        : "+f"(c[0]), "+f"(c[1]), "+f"(c[2]), "+f"(c[3])
        : "r"(a[0]), "r"(a[1]), "r"(a[2]), "r"(a[3]), "r"(b[0]), "r"(b[1]));
}

__device__ __forceinline__ void cp16(uint32_t saddr, const void* g)
{
    asm volatile("cp.async.cg.shared.global [%0], [%1], 16;"
        :: "r"(saddr), "l"(g) : "memory");
}
#define CP_COMMIT() asm volatile("cp.async.commit_group;" ::: "memory")
#define CP_WAIT1()  asm volatile("cp.async.wait_group 1;" ::: "memory")
#define CP_WAIT0()  asm volatile("cp.async.wait_group 0;" ::: "memory")

__device__ __forceinline__ uint32_t pack2(float x, float y)
{
    __nv_bfloat16 h0 = __float2bfloat16(x);
    __nv_bfloat16 h1 = __float2bfloat16(y);
    return (uint32_t)__bfloat16_as_ushort(h0) | ((uint32_t)__bfloat16_as_ushort(h1) << 16);
}

// split pair into bf16 hi/lo packed words
__device__ __forceinline__ void split2(float a, float b, uint32_t* hi, uint32_t* lo)
{
    __nv_bfloat16 ha = __float2bfloat16(a);
    __nv_bfloat16 hb = __float2bfloat16(b);
    *hi = (uint32_t)__bfloat16_as_ushort(ha) | ((uint32_t)__bfloat16_as_ushort(hb) << 16);
    *lo = pack2(a - __bfloat162float(ha), b - __bfloat162float(hb));
}

// pack pair into fp16 word
__device__ __forceinline__ uint32_t pack2h(float a, float b)
{
    __half ha = __float2half_rn(a);
    __half hb = __float2half_rn(b);
    return (uint32_t)__half_as_ushort(ha) | ((uint32_t)__half_as_ushort(hb) << 16);
}

// ---------------------------------------------------------------------------
// convert fp32 -> fp16 (same layout)
// ---------------------------------------------------------------------------
__global__ void cvt_f16(const float* __restrict__ in, __half* __restrict__ out)
{
    const int i = blockIdx.x * blockDim.x + threadIdx.x;
    float4 v = ((const float4*)in)[i];
    uint2 o;
    o.x = pack2h(v.x, v.y);
    o.y = pack2h(v.z, v.w);
    ((uint2*)out)[i] = o;
}

// transpose 4 weights at once: W[K][N] -> WT[N][K] fp16 (blockIdx.y selects)
__global__ void whalfT4(const float* __restrict__ W0, const float* __restrict__ W1,
                        const float* __restrict__ W2, const float* __restrict__ W3,
                        __half* __restrict__ Wt)
{
    const int id = blockIdx.x * blockDim.x + threadIdx.x;
    const int w  = blockIdx.y;
    const float* W = (w == 0) ? W0 : (w == 1) ? W1 : (w == 2) ? W2 : W3;
    const int n = id / EDIM;
    const int k = id % EDIM;
    Wt[(size_t)w * WSZ + id] = __float2half_rn(W[k * EDIM + n]);
}

// ---------------------------------------------------------------------------
// fp16 single-product GEMM: C = A @ B^T_layout (+bias), A and B both fp16.
// Wt holds B transposed [N][K]. 3-stage cp.async pipeline, ONE barrier per
// K-iteration (stage(it+2) buffer was last computed at it-1, so the top
// barrier covers both the visibility and WAR hazards).
// mode 0: fp32 C.  mode 1: bf16 split (Chi/Clo).  mode 2: rope + bf16 split.
// ---------------------------------------------------------------------------
#define ASTR   40
#define TBYTES (128 * ASTR * 2)          // 10240
#define NSTG   3
#define GEMM_SMEM (NSTG * 2 * TBYTES)    // 61440

__global__ __launch_bounds__(256, 2) void gemm_f16(
    const __half* __restrict__ Ah, const __half* __restrict__ Wt,
    const float* __restrict__ bias, int mode, float* __restrict__ C,
    __nv_bfloat16* __restrict__ Chi, __nv_bfloat16* __restrict__ Clo,
    int M, int N, int K)
{
    extern __shared__ char sm[];

    const int tid  = threadIdx.x;
    const int bm   = blockIdx.y * 128;
    const int bn   = blockIdx.x * 128;
    const int warp = tid >> 5;
    const int lane = tid & 31;
    const int wm   = warp >> 2;
    const int wn   = warp & 3;

    const int r  = tid >> 1;
    const int ch = (tid & 1) * 16;

    const __half* gA = Ah + (size_t)(bm + r) * K + ch;
    const __half* gB = Wt + (size_t)(bn + r) * K + ch;

    const uint32_t sb     = smem_u32(sm);
    const uint32_t st_off = (uint32_t)((r * ASTR + ch) * 2);

    const int lane15 = lane & 15;
    const uint32_t aoff = (uint32_t)((wm * 64 + lane15) * 80 + (lane >> 4) * 16);
    const uint32_t boff = (uint32_t)((wn * 32 + (lane15 & 7)) * 80 + ((lane15 >> 3) & 1) * 16);

    float acc[4][4][4];
    #pragma unroll
    for (int i = 0; i < 4; i++) {
        #pragma unroll
        for (int j = 0; j < 4; j++) {
            #pragma unroll
            for (int e = 0; e < 4; e++) {
                acc[i][j][e] = 0.0f;
            }
        }
    }

    const int NIT = K / 32;   // 24

    // prologue: stages 0 and 1, one commit group each
    #pragma unroll
    for (int p = 0; p < 2; p++) {
        const uint32_t base = sb + (uint32_t)(p * 2) * TBYTES + st_off;
        const int kt = p * 32;
        cp16(base + 0 * TBYTES,      gA + kt);
        cp16(base + 0 * TBYTES + 16, gA + kt + 8);
        cp16(base + 1 * TBYTES,      gB + kt);
        cp16(base + 1 * TBYTES + 16, gB + kt + 8);
        CP_COMMIT();
    }

    int s = 0;   // stage index = it % 3
    for (int it = 0; it < NIT; it++) {
        if (it == NIT - 1) {
            CP_WAIT0();
        } else {
            CP_WAIT1();
        }
        __syncthreads();

        if (it + 2 < NIT) {
            int sp = s + 2;
            if (sp >= NSTG) sp -= NSTG;
            const int kt = (it + 2) * 32;
            const uint32_t base = sb + (uint32_t)(sp * 2) * TBYTES + st_off;
            cp16(base + 0 * TBYTES,      gA + kt);
            cp16(base + 0 * TBYTES + 16, gA + kt + 8);
            cp16(base + 1 * TBYTES,      gB + kt);
            cp16(base + 1 * TBYTES + 16, gB + kt + 8);
            CP_COMMIT();
        }

        const uint32_t baA = sb + (uint32_t)(s * 2 + 0) * TBYTES;
        const uint32_t baB = sb + (uint32_t)(s * 2 + 1) * TBYTES;

        #pragma unroll
        for (int ks = 0; ks < 2; ks++) {
            const uint32_t kb = (uint32_t)(ks * 32);
            uint32_t ah[4][4];
            uint32_t bf[4][2];
            #pragma unroll
            for (int mf = 0; mf < 4; mf++) {
                ldsm_x4(ah[mf], baA + aoff + mf * 1280 + kb);
            }
            #pragma unroll
            for (int nf = 0; nf < 4; nf++) {
                ldsm_x2(bf[nf], baB + boff + nf * 640 + kb);
            }
            #pragma unroll
            for (int mf = 0; mf < 4; mf++) {
                #pragma unroll
                for (int nf = 0; nf < 4; nf++) {
                    mma16816h(acc[mf][nf], ah[mf], bf[nf]);
                }
            }
        }

        s++;
        if (s >= NSTG) s -= NSTG;
    }

    const int rbase = bm + wm * 64 + (lane >> 2);
    const int cbase = bn + wn * 32 + (lane & 3) * 2;
    #pragma unroll
    for (int nf = 0; nf < 4; nf++) {
        const int col = cbase + nf * 8;
        float bb0 = 0.0f;
        float bb1 = 0.0f;
        if (bias != 0) {
            bb0 = bias[col];
            bb1 = bias[col + 1];
        }
        // rope frequency for this column pair (mode 2)
        const int hd = col & 63;
        const int pr = hd >> 1;
        const int jf = pr & 15;
        const float invf = __expf(-0.57564627324851142f * (float)jf);

        #pragma unroll
        for (int mf = 0; mf < 4; mf++) {
            const int row = rbase + mf * 16;
            float a0 = acc[mf][nf][0] + bb0;
            float a1 = acc[mf][nf][1] + bb1;
            float a2 = acc[mf][nf][2] + bb0;
            float a3 = acc[mf][nf][3] + bb1;

            if (mode == 2) {
                const int p0 = row & 255;
                const int p8 = (row + 8) & 255;
                const float pos0 = (pr < 16) ? (float)(p0 & 15) : (float)(p0 >> 4);
                const float pos8 = (pr < 16) ? (float)(p8 & 15) : (float)(p8 >> 4);
                float s0, c0, s8, c8;
                sincosf(pos0 * invf, &s0, &c0);
                sincosf(pos8 * invf, &s8, &c8);
                const float r0 = a0 * c0 - a1 * s0;
                const float r1 = a1 * c0 + a0 * s0;
                const float r2 = a2 * c8 - a3 * s8;
                const float r3 = a3 * c8 + a2 * s8;
                a0 = r0; a1 = r1; a2 = r2; a3 = r3;
            }

            if (mode >= 1) {
                uint32_t h0, l0, h1, l1;
                split2(a0, a1, &h0, &l0);
                split2(a2, a3, &h1, &l1);
                *(uint32_t*)(Chi + (size_t)row * N + col)       = h0;
                *(uint32_t*)(Clo + (size_t)row * N + col)       = l0;
                *(uint32_t*)(Chi + (size_t)(row + 8) * N + col) = h1;
                *(uint32_t*)(Clo + (size_t)(row + 8) * N + col) = l1;
            } else {
                float2 v0;
                float2 v1;
                v0.x = a0; v0.y = a1;
                v1.x = a2; v1.y = a3;
                *(float2*)(C + (size_t)row * N + col)       = v0;
                *(float2*)(C + (size_t)(row + 8) * N + col) = v1;
            }
        }
    }
}

// ---------------------------------------------------------------------------
// Tensor-core attention (bf16 hi/lo 3-product, unchanged math).
// Writes y as single fp16 for the output GEMM.
// ---------------------------------------------------------------------------
#define SROWB   144
#define ATILEB  (64 * SROWB)
#define ASTGB   (4 * ATILEB)
#define ATTN_SMEM (2 * ASTGB)

__global__ __launch_bounds__(256, 1) void attn_mma(
    const __nv_bfloat16* __restrict__ qhi, const __nv_bfloat16* __restrict__ qlo,
    const __nv_bfloat16* __restrict__ khi, const __nv_bfloat16* __restrict__ klo,
    const __nv_bfloat16* __restrict__ vhi, const __nv_bfloat16* __restrict__ vlo,
    __half* __restrict__ yh)
{
    extern __shared__ char sm[];

    const int tid   = threadIdx.x;
    const int warp  = tid >> 5;
    const int lane  = tid & 31;
    const int l4    = lane >> 2;
    const int l2    = (lane & 3) * 2;
    const int lane15 = lane & 15;

    const int bt   = blockIdx.x;
    const int h    = blockIdx.y >> 1;
    const int half = blockIdx.y & 1;

    const int qrow0 = bt * 256 + half * 128 + warp * 16;
    const uint32_t sb = smem_u32(sm);

    uint32_t qh[4][4];
    uint32_t ql[4][4];
    {
        const size_t qb = (size_t)(qrow0 + l4) * EDIM + h * 64;
        #pragma unroll
        for (int kf = 0; kf < 4; kf++) {
            const int c = kf * 16 + l2;
            qh[kf][0] = *(const uint32_t*)(qhi + qb + c);
            qh[kf][1] = *(const uint32_t*)(qhi + qb + (size_t)8 * EDIM + c);
            qh[kf][2] = *(const uint32_t*)(qhi + qb + c + 8);
            qh[kf][3] = *(const uint32_t*)(qhi + qb + (size_t)8 * EDIM + c + 8);
            ql[kf][0] = *(const uint32_t*)(qlo + qb + c);
            ql[kf][1] = *(const uint32_t*)(qlo + qb + (size_t)8 * EDIM + c);
            ql[kf][2] = *(const uint32_t*)(qlo + qb + c + 8);
            ql[kf][3] = *(const uint32_t*)(qlo + qb + (size_t)8 * EDIM + c + 8);
        }
    }

    float O[8][4];
    #pragma unroll
    for (int nf = 0; nf < 8; nf++) {
        #pragma unroll
        for (int e = 0; e < 4; e++) {
            O[nf][e] = 0.0f;
        }
    }
    float sum0 = 0.0f;
    float sum1 = 0.0f;

    const int lrow0 = tid >> 3;
    const int lseg0 = tid & 7;
    const int lrow1 = (tid + 256) >> 3;
    const int lseg1 = tid & 7;

    #define ATTN_LOAD(c, s) do {                                                   \
        const int jg0 = bt * 256 + (c) * 64;                                        \
        const uint32_t base = sb + (uint32_t)(s) * ASTGB;                           \
        size_t g0 = (size_t)(jg0 + lrow0) * EDIM + h * 64 + lseg0 * 8;              \
        uint32_t d0 = base + (uint32_t)(lrow0 * SROWB + lseg0 * 16);                \
        cp16(d0 + 0 * ATILEB, khi + g0);                                            \
        cp16(d0 + 1 * ATILEB, klo + g0);                                            \
        cp16(d0 + 2 * ATILEB, vhi + g0);                                            \
        cp16(d0 + 3 * ATILEB, vlo + g0);                                            \
        size_t g1 = (size_t)(jg0 + lrow1) * EDIM + h * 64 + lseg1 * 8;              \
        uint32_t d1 = base + (uint32_t)(lrow1 * SROWB + lseg1 * 16);                \
        cp16(d1 + 0 * ATILEB, khi + g1);                                            \
        cp16(d1 + 1 * ATILEB, klo + g1);                                            \
        cp16(d1 + 2 * ATILEB, vhi + g1);                                            \
        cp16(d1 + 3 * ATILEB, vlo + g1);                                            \
        CP_COMMIT();                                                                \
    } while (0)

    ATTN_LOAD(0, 0);

    const uint32_t bqoff = (uint32_t)((lane15 & 7) * SROWB + ((lane15 >> 3) & 1) * 16);
    const uint32_t bvoff = (uint32_t)(lane15 * SROWB);

    for (int c = 0; c < 4; c++) {
        const int s = c & 1;
        if (c < 3) {
            ATTN_LOAD(c + 1, s ^ 1);
            CP_WAIT1();
        } else {
            CP_WAIT0();
        }
        __syncthreads();

        const uint32_t kb = sb + (uint32_t)s * ASTGB;

        float S[8][4];
        #pragma unroll
        for (int nf = 0; nf < 8; nf++) {
            #pragma unroll
            for (int e = 0; e < 4; e++) {
                S[nf][e] = 0.0f;
            }
        }
        #pragma unroll
        for (int nf = 0; nf < 8; nf++) {
            uint32_t bh[4][2];
            uint32_t bl[4][2];
            #pragma unroll
            for (int kf = 0; kf < 4; kf++) {
                const uint32_t a = kb + (uint32_t)(nf * 8 * SROWB + kf * 32) + bqoff;
                ldsm_x2(bh[kf], a);
                ldsm_x2(bl[kf], a + ATILEB);
            }
            #pragma unroll
            for (int kf = 0; kf < 4; kf++) {
                mma16816(S[nf], qh[kf], bh[kf]);
                mma16816(S[nf], qh[kf], bl[kf]);
                mma16816(S[nf], ql[kf], bh[kf]);
            }
        }

        uint32_t ph[4][4];
        uint32_t pl[4][4];
        #pragma unroll
        for (int nf = 0; nf < 8; nf++) {
            float p0 = __expf(S[nf][0] * 0.125f);
            float p1 = __expf(S[nf][1] * 0.125f);
            float p2 = __expf(S[nf][2] * 0.125f);
            float p3 = __expf(S[nf][3] * 0.125f);
            sum0 += p0 + p1;
            sum1 += p2 + p3;
            const int kf2 = nf >> 1;
            const int o   = (nf & 1) * 2;
            split2(p0, p1, &ph[kf2][o],     &pl[kf2][o]);
            split2(p2, p3, &ph[kf2][o + 1], &pl[kf2][o + 1]);
        }

        #pragma unroll
        for (int nf = 0; nf < 8; nf++) {
            #pragma unroll
            for (int kf = 0; kf < 4; kf++) {
                uint32_t vh2[2];
                uint32_t vl2[2];
                const uint32_t a = kb + 2 * ATILEB +
                                   (uint32_t)(kf * 16 * SROWB + nf * 16) + bvoff;
                ldsm_x2t(vh2, a);
                ldsm_x2t(vl2, a + ATILEB);
                mma16816(O[nf], ph[kf], vh2);
                mma16816(O[nf], ph[kf], vl2);
                mma16816(O[nf], pl[kf], vh2);
            }
        }
        __syncthreads();
    }

    sum0 += __shfl_xor_sync(0xffffffffu, sum0, 1);
    sum0 += __shfl_xor_sync(0xffffffffu, sum0, 2);
    sum1 += __shfl_xor_sync(0xffffffffu, sum1, 1);
    sum1 += __shfl_xor_sync(0xffffffffu, sum1, 2);
    const float inv0 = 1.0f / sum0;
    const float inv1 = 1.0f / sum1;

    const size_t r0 = (size_t)(qrow0 + l4) * EDIM;
    const size_t r1 = r0 + (size_t)8 * EDIM;
    #pragma unroll
    for (int nf = 0; nf < 8; nf++) {
        const int col = h * 64 + nf * 8 + l2;
        *(uint32_t*)(yh + r0 + col) = pack2h(O[nf][0] * inv0, O[nf][1] * inv0);
        *(uint32_t*)(yh + r1 + col) = pack2h(O[nf][2] * inv1, O[nf][3] * inv1);
    }
}

// ---------------------------------------------------------------------------
extern "C" void kernel_launch(void* const* d_in, const int* in_sizes, int n_in,
                              void* d_out, int out_size)
{
    const float* x  = (const float*)d_in[0];
    const float* Wq = (const float*)d_in[1];
    const float* bq = (const float*)d_in[2];
    const float* Wk = (const float*)d_in[3];
    const float* bk = (const float*)d_in[4];
    const float* Wv = (const float*)d_in[5];
    const float* bv = (const float*)d_in[6];
    const float* Wo = (const float*)d_in[7];
    float* out = (float*)d_out;

    __half *xh = 0, *yh = 0, *wt = 0;
    __nv_bfloat16 *qhi = 0, *qlo = 0, *khi = 0, *klo = 0, *vhi = 0, *vlo = 0;
    cudaGetSymbolAddress((void**)&xh,  g_xh);
    cudaGetSymbolAddress((void**)&yh,  g_yh);
    cudaGetSymbolAddress((void**)&wt,  g_wt);
    cudaGetSymbolAddress((void**)&qhi, g_qhi);
    cudaGetSymbolAddress((void**)&qlo, g_qlo);
    cudaGetSymbolAddress((void**)&khi, g_khi);
    cudaGetSymbolAddress((void**)&klo, g_klo);
    cudaGetSymbolAddress((void**)&vhi, g_vhi);
    cudaGetSymbolAddress((void**)&vlo, g_vlo);

    cudaFuncSetAttribute(gemm_f16, cudaFuncAttributeMaxDynamicSharedMemorySize, GEMM_SMEM);
    cudaFuncSetAttribute(attn_mma, cudaFuncAttributeMaxDynamicSharedMemorySize, ATTN_SMEM);

    cvt_f16<<<(M_ROWS * EDIM / 4) / 256, 256>>>(x, xh);
    whalfT4<<<dim3(WSZ / 256, 4), 256>>>(Wq, Wk, Wv, Wo, wt);

    dim3 gg(EDIM / 128, M_ROWS / 128);

    // Q: GEMM + bias + rope -> bf16 split
    gemm_f16<<<gg, 256, GEMM_SMEM>>>(xh, wt + 0 * WSZ, bq, 2,
                                     (float*)0, qhi, qlo, M_ROWS, EDIM, EDIM);
    // K: GEMM + bias + rope -> bf16 split
    gemm_f16<<<gg, 256, GEMM_SMEM>>>(xh, wt + 1 * WSZ, bk, 2,
                                     (float*)0, khi, klo, M_ROWS, EDIM, EDIM);
    // V: GEMM + bias -> bf16 split
    gemm_f16<<<gg, 256, GEMM_SMEM>>>(xh, wt + 2 * WSZ, bv, 1,
                                     (float*)0, vhi, vlo, M_ROWS, EDIM, EDIM);

    attn_mma<<<dim3(BT, NHEAD * 2), 256, ATTN_SMEM>>>(qhi, qlo, khi, klo, vhi, vlo, yh);

    // output GEMM -> fp32
    gemm_f16<<<gg, 256, GEMM_SMEM>>>(yh, wt + 3 * WSZ, (const float*)0, 0,
                                     out, (__nv_bfloat16*)0, (__nv_bfloat16*)0, M_ROWS, EDIM, EDIM);
}